// round 10
// baseline (speedup 1.0000x reference)
#include <cuda_runtime.h>
#include <cuda_bf16.h>
#include <cstdint>
#include <math.h>

// ---------------------------------------------------------------------------
// Self-attention B=4, S=2048, D=1024 — Round 9.
// Revert to R7 GEMM shape (128x64 block, 4 warps 64x32, BKE=64, 2-stage
// cp.async, 2 CTAs/SM) + NEW: fragment double-buffering across ks-steps
// (load ks+1's ldmatrix fragments while computing ks's MMAs).
// ---------------------------------------------------------------------------

#define BATCH 4
#define SEQ   2048
#define DIM   1024

typedef __nv_bfloat16 bf16;

// ---------------- scratch ---------------------------------------------------
__device__ bf16  g_ah[BATCH * SEQ * DIM], g_al[BATCH * SEQ * DIM];
__device__ bf16  g_wth[3 * DIM * DIM],    g_wtl[3 * DIM * DIM];
__device__ bf16  g_qh[BATCH * SEQ * DIM], g_ql[BATCH * SEQ * DIM];
__device__ bf16  g_kh[BATCH * SEQ * DIM], g_kl[BATCH * SEQ * DIM];
__device__ bf16  g_vh[BATCH * SEQ * DIM], g_vl[BATCH * SEQ * DIM];
__device__ bf16  g_vth[BATCH * DIM * SEQ], g_vtl[BATCH * DIM * SEQ];
__device__ float g_s [BATCH * SEQ * SEQ];
__device__ bf16  g_ph[BATCH * SEQ * SEQ], g_pl[BATCH * SEQ * SEQ];

// ---------------- helpers ---------------------------------------------------
__device__ __forceinline__ uint32_t smem_u32(const void* p) {
    uint32_t a;
    asm("{ .reg .u64 t; cvta.to.shared.u64 t, %1; cvt.u32.u64 %0, t; }"
        : "=r"(a) : "l"(p));
    return a;
}
__device__ __forceinline__ void cp16(uint32_t dst, const void* src) {
    asm volatile("cp.async.cg.shared.global [%0], [%1], 16;"
                 :: "r"(dst), "l"(src));
}
#define CP_COMMIT() asm volatile("cp.async.commit_group;" ::: "memory")
#define CP_WAIT(n)  asm volatile("cp.async.wait_group %0;" :: "n"(n) : "memory")

__device__ __forceinline__ void ldm_x4(uint32_t* r, uint32_t addr) {
    asm volatile("ldmatrix.sync.aligned.m8n8.x4.shared.b16 {%0,%1,%2,%3}, [%4];"
                 : "=r"(r[0]), "=r"(r[1]), "=r"(r[2]), "=r"(r[3]) : "r"(addr));
}
__device__ __forceinline__ void mma_bf16(float* c, const uint32_t* a,
                                         const uint32_t* b) {
    asm volatile(
        "mma.sync.aligned.m16n8k16.row.col.f32.bf16.bf16.f32 "
        "{%0,%1,%2,%3}, {%4,%5,%6,%7}, {%8,%9}, {%0,%1,%2,%3};"
        : "+f"(c[0]), "+f"(c[1]), "+f"(c[2]), "+f"(c[3])
        : "r"(a[0]), "r"(a[1]), "r"(a[2]), "r"(a[3]), "r"(b[0]), "r"(b[1]));
}
__device__ __forceinline__ uint32_t bpack(bf16 a, bf16 b) {
    union { __nv_bfloat162 v; uint32_t u; } t;
    t.v = __halves2bfloat162(a, b);
    return t.u;
}
__device__ __forceinline__ void split2(float x, float y, uint32_t& hi,
                                       uint32_t& lo) {
    bf16 hx = __float2bfloat16(x), hy = __float2bfloat16(y);
    hi = bpack(hx, hy);
    lo = bpack(__float2bfloat16(x - __bfloat162float(hx)),
               __float2bfloat16(y - __bfloat162float(hy)));
}

// ---------------- GEMM config ----------------------------------------------
#define BM 128
#define BN 64
#define BKE 64                 // bf16 elems per stage (4 x k16)
#define GTHREADS 128           // 4 warps: 2(M) x 2(N), warp tile 64x32

#define ROWB   144             // 128B data + 16B pad
#define AT_B   (128 * ROWB)
#define BT_B   (64 * ROWB)
#define ST_AHI 0
#define ST_ALO (AT_B)
#define ST_BHI (2 * AT_B)
#define ST_BLO (2 * AT_B + BT_B)
#define STAGEB (2 * AT_B + 2 * BT_B)        // 55296
#define SMEM_SZ (2 * STAGEB)                // 110592 -> 2 CTAs/SM

template<int R>
__device__ __forceinline__ void issue_tile(const bf16* src, uint32_t dst,
                                           int K, long k0, int tid) {
#pragma unroll
    for (int it = 0; it < R * 8 / GTHREADS; it++) {
        int c = tid + it * GTHREADS;
        int row = c >> 3, col = c & 7;
        cp16(dst + row * ROWB + col * 16, src + (long)row * K + k0 + col * 8);
    }
}

// load one ks-step's fragments (A hi/lo 4x ldm each, B hi/lo 2x ldm each)
__device__ __forceinline__ void load_frags(
    uint32_t st, int ks, uint32_t partA, uint32_t partB,
    uint32_t ah[4][4], uint32_t al[4][4],
    uint32_t bh[4][2], uint32_t bl[4][2])
{
#pragma unroll
    for (int mf = 0; mf < 4; mf++) {
        uint32_t off = (uint32_t)(mf * 16 * ROWB + ks * 32) + partA;
        ldm_x4(ah[mf], st + ST_AHI + off);
        ldm_x4(al[mf], st + ST_ALO + off);
    }
#pragma unroll
    for (int nf2 = 0; nf2 < 2; nf2++) {
        uint32_t off = (uint32_t)(nf2 * 16 * ROWB + ks * 32) + partB;
        uint32_t t[4];
        ldm_x4(t, st + ST_BHI + off);
        bh[nf2 * 2][0] = t[0]; bh[nf2 * 2][1] = t[1];
        bh[nf2 * 2 + 1][0] = t[2]; bh[nf2 * 2 + 1][1] = t[3];
        ldm_x4(t, st + ST_BLO + off);
        bl[nf2 * 2][0] = t[0]; bl[nf2 * 2][1] = t[1];
        bl[nf2 * 2 + 1][0] = t[2]; bl[nf2 * 2 + 1][1] = t[3];
    }
}

// NT GEMM: C[m][n] = sum_k A[m][k]*B[n][k]; A,B as hi/lo bf16 pairs.
template<bool HAS_BIAS, bool SPLIT_OUT>
__global__ void __launch_bounds__(GTHREADS, 2)
bf16x3_gemm(const bf16* __restrict__ Ah, const bf16* __restrict__ Al,
            const bf16* __restrict__ Bh, const bf16* __restrict__ Bl,
            const float* __restrict__ bias,
            float* __restrict__ Cf, bf16* __restrict__ Ch,
            bf16* __restrict__ Cl,
            int M, int N, int K, long sA, long sB, long sC)
{
    extern __shared__ char smem[];
    const uint32_t sbase = smem_u32(smem);
    const int tid  = threadIdx.x;
    const int lane = tid & 31;
    const int wid  = tid >> 5;
    const int wm0  = (wid >> 1) * 64;
    const int wn0  = (wid & 1) * 32;
    const int m0 = blockIdx.y * BM;
    const int n0 = blockIdx.x * BN;

    const bf16* Ahb = Ah + (long)blockIdx.z * sA + (long)m0 * K;
    const bf16* Alb = Al + (long)blockIdx.z * sA + (long)m0 * K;
    const bf16* Bhb = Bh + (long)blockIdx.z * sB + (long)n0 * K;
    const bf16* Blb = Bl + (long)blockIdx.z * sB + (long)n0 * K;

    const uint32_t partA = (uint32_t)((wm0 + (lane & 15)) * ROWB
                                      + ((lane >> 4) << 4));
    const uint32_t partB = (uint32_t)((wn0 + (lane & 7) + ((lane >> 4) << 3)) * ROWB
                                      + ((lane & 8) ? 16 : 0));

    float acc[4][4][4];
#pragma unroll
    for (int i = 0; i < 4; i++)
#pragma unroll
        for (int j = 0; j < 4; j++)
#pragma unroll
            for (int r = 0; r < 4; r++) acc[i][j][r] = 0.f;

    const int NC = K / BKE;

    // prologue: stage 0
    issue_tile<128>(Ahb, sbase + ST_AHI, K, 0, tid);
    issue_tile<128>(Alb, sbase + ST_ALO, K, 0, tid);
    issue_tile<64> (Bhb, sbase + ST_BHI, K, 0, tid);
    issue_tile<64> (Blb, sbase + ST_BLO, K, 0, tid);
    CP_COMMIT();

    // double-buffered fragment sets
    uint32_t ah[2][4][4], al[2][4][4], bh[2][4][2], bl[2][4][2];

    for (int i = 0; i < NC; i++) {
        __syncthreads();
        if (i + 1 < NC) {
            uint32_t sb = sbase + (uint32_t)(((i + 1) & 1) * STAGEB);
            long k0 = (long)(i + 1) * BKE;
            issue_tile<128>(Ahb, sb + ST_AHI, K, k0, tid);
            issue_tile<128>(Alb, sb + ST_ALO, K, k0, tid);
            issue_tile<64> (Bhb, sb + ST_BHI, K, k0, tid);
            issue_tile<64> (Blb, sb + ST_BLO, K, k0, tid);
            CP_COMMIT();
            CP_WAIT(1);
        } else {
            CP_WAIT(0);
        }
        __syncthreads();

        const uint32_t st = sbase + (uint32_t)((i & 1) * STAGEB);

        // software-pipelined fragment loads across the 4 ks steps
        load_frags(st, 0, partA, partB, ah[0], al[0], bh[0], bl[0]);
#pragma unroll
        for (int ks = 0; ks < 4; ks++) {
            const int cur = ks & 1, nxt = cur ^ 1;
            if (ks < 3)
                load_frags(st, ks + 1, partA, partB,
                           ah[nxt], al[nxt], bh[nxt], bl[nxt]);
#pragma unroll
            for (int nf = 0; nf < 4; nf++)
#pragma unroll
                for (int mf = 0; mf < 4; mf++) {
                    mma_bf16(acc[mf][nf], ah[cur][mf], bh[cur][nf]);
                    mma_bf16(acc[mf][nf], ah[cur][mf], bl[cur][nf]);
                    mma_bf16(acc[mf][nf], al[cur][mf], bh[cur][nf]);
                }
        }
    }

    // epilogue
    const int gid = lane >> 2, tig = lane & 3;
#pragma unroll
    for (int mf = 0; mf < 4; mf++) {
        int r0 = m0 + wm0 + mf * 16 + gid;
#pragma unroll
        for (int nf = 0; nf < 4; nf++) {
            int c0 = n0 + wn0 + nf * 8 + tig * 2;
            float bx = 0.f, by = 0.f;
            if (HAS_BIAS) { bx = bias[c0]; by = bias[c0 + 1]; }
            float x0 = acc[mf][nf][0] + bx, y0 = acc[mf][nf][1] + by;
            float x1 = acc[mf][nf][2] + bx, y1 = acc[mf][nf][3] + by;
            if (SPLIT_OUT) {
                long o0 = (long)(r0) * N + c0 + (long)blockIdx.z * sC;
                long o1 = (long)(r0 + 8) * N + c0 + (long)blockIdx.z * sC;
                uint32_t h, l;
                split2(x0, y0, h, l);
                *(uint32_t*)(Ch + o0) = h; *(uint32_t*)(Cl + o0) = l;
                split2(x1, y1, h, l);
                *(uint32_t*)(Ch + o1) = h; *(uint32_t*)(Cl + o1) = l;
            } else {
                float* Cb = Cf + (long)blockIdx.z * sC;
                *(float2*)(Cb + (long)r0 * N + c0) = make_float2(x0, y0);
                *(float2*)(Cb + (long)(r0 + 8) * N + c0) = make_float2(x1, y1);
            }
        }
    }
}

// ---------------- split a ---------------------------------------------------
__global__ void __launch_bounds__(256)
split_kernel(const float* __restrict__ src, bf16* __restrict__ h,
             bf16* __restrict__ l)
{
    long idx = (long)blockIdx.x * 256 + threadIdx.x;
    float2 v = ((const float2*)src)[idx];
    uint32_t hw, lw;
    split2(v.x, v.y, hw, lw);
    ((uint32_t*)h)[idx] = hw;
    ((uint32_t*)l)[idx] = lw;
}

// ---------------- weight transpose + split ----------------------------------
__global__ void __launch_bounds__(256)
wsplit_kernel(const float* __restrict__ w, bf16* __restrict__ h,
              bf16* __restrict__ l)
{
    __shared__ float t[32][33];
    int x = blockIdx.x * 32 + threadIdx.x;
    int y = blockIdx.y * 32 + threadIdx.y;
#pragma unroll
    for (int j = 0; j < 32; j += 8)
        t[threadIdx.y + j][threadIdx.x] = w[(long)(y + j) * DIM + x];
    __syncthreads();
    x = blockIdx.y * 32 + threadIdx.x;
    y = blockIdx.x * 32 + threadIdx.y;
#pragma unroll
    for (int j = 0; j < 32; j += 8) {
        float v = t[threadIdx.x][threadIdx.y + j];
        bf16 hv = __float2bfloat16(v);
        h[(long)(y + j) * DIM + x] = hv;
        l[(long)(y + j) * DIM + x] =
            __float2bfloat16(v - __bfloat162float(hv));
    }
}

// ---------------- bf16 transpose --------------------------------------------
__global__ void __launch_bounds__(256)
transpose_bf16(const uint16_t* __restrict__ src, uint16_t* __restrict__ dst,
               int R, int C, long sS, long sD)
{
    __shared__ uint16_t t[32][33];
    src += (long)blockIdx.z * sS;
    dst += (long)blockIdx.z * sD;
    int x = blockIdx.x * 32 + threadIdx.x;
    int y = blockIdx.y * 32 + threadIdx.y;
#pragma unroll
    for (int j = 0; j < 32; j += 8)
        t[threadIdx.y + j][threadIdx.x] = src[(long)(y + j) * C + x];
    __syncthreads();
    x = blockIdx.y * 32 + threadIdx.x;
    y = blockIdx.x * 32 + threadIdx.y;
#pragma unroll
    for (int j = 0; j < 32; j += 8)
        dst[(long)(y + j) * R + x] = t[threadIdx.x][threadIdx.y + j];
}

// ---------------- softmax -> hi/lo ------------------------------------------
__global__ void __launch_bounds__(256)
softmax_split(const float* __restrict__ S, bf16* __restrict__ Ph,
              bf16* __restrict__ Pl)
{
    const float2* row = (const float2*)(S + (long)blockIdx.x * SEQ);
    uint32_t* oh = (uint32_t*)(Ph + (long)blockIdx.x * SEQ);
    uint32_t* ol = (uint32_t*)(Pl + (long)blockIdx.x * SEQ);
    __shared__ float red[256];
    const int tid = threadIdx.x;

    float2 e[4];
#pragma unroll
    for (int j = 0; j < 4; j++) e[j] = row[tid + j * 256];

    float m = -INFINITY;
#pragma unroll
    for (int j = 0; j < 4; j++) m = fmaxf(m, fmaxf(e[j].x, e[j].y));
    red[tid] = m;
    __syncthreads();
    for (int s = 128; s > 0; s >>= 1) {
        if (tid < s) red[tid] = fmaxf(red[tid], red[tid + s]);
        __syncthreads();
    }
    m = red[0];
    __syncthreads();

    float sum = 0.f;
#pragma unroll
    for (int j = 0; j < 4; j++) {
        e[j].x = __expf(e[j].x - m);
        e[j].y = __expf(e[j].y - m);
        sum += e[j].x + e[j].y;
    }
    red[tid] = sum;
    __syncthreads();
    for (int s = 128; s > 0; s >>= 1) {
        if (tid < s) red[tid] += red[tid + s];
        __syncthreads();
    }
    float inv = 1.f / red[0];

#pragma unroll
    for (int j = 0; j < 4; j++) {
        uint32_t h, l;
        split2(e[j].x * inv, e[j].y * inv, h, l);
        oh[tid + j * 256] = h;
        ol[tid + j * 256] = l;
    }
}

// ---------------------------------------------------------------------------
extern "C" void kernel_launch(void* const* d_in, const int* in_sizes, int n_in,
                              void* d_out, int out_size)
{
    const float* a   = (const float*)d_in[0];
    const float* w_q = (const float*)d_in[1];
    const float* b_q = (const float*)d_in[2];
    const float* w_k = (const float*)d_in[3];
    const float* b_k = (const float*)d_in[4];
    const float* w_v = (const float*)d_in[5];
    const float* b_v = (const float*)d_in[6];
    float* out = (float*)d_out;

    bf16 *ah, *al, *wth, *wtl, *qh, *ql, *kh, *kl, *vh, *vl, *vth, *vtl, *ph, *pl;
    float* s;
    cudaGetSymbolAddress((void**)&ah,  g_ah);  cudaGetSymbolAddress((void**)&al,  g_al);
    cudaGetSymbolAddress((void**)&wth, g_wth); cudaGetSymbolAddress((void**)&wtl, g_wtl);
    cudaGetSymbolAddress((void**)&qh,  g_qh);  cudaGetSymbolAddress((void**)&ql,  g_ql);
    cudaGetSymbolAddress((void**)&kh,  g_kh);  cudaGetSymbolAddress((void**)&kl,  g_kl);
    cudaGetSymbolAddress((void**)&vh,  g_vh);  cudaGetSymbolAddress((void**)&vl,  g_vl);
    cudaGetSymbolAddress((void**)&vth, g_vth); cudaGetSymbolAddress((void**)&vtl, g_vtl);
    cudaGetSymbolAddress((void**)&ph,  g_ph);  cudaGetSymbolAddress((void**)&pl,  g_pl);
    cudaGetSymbolAddress((void**)&s,   g_s);

    cudaFuncSetAttribute(bf16x3_gemm<true, true>,
                         cudaFuncAttributeMaxDynamicSharedMemorySize, SMEM_SZ);
    cudaFuncSetAttribute(bf16x3_gemm<false, false>,
                         cudaFuncAttributeMaxDynamicSharedMemorySize, SMEM_SZ);

    const int M1 = BATCH * SEQ;   // 8192

    // 0) operand prep
    split_kernel<<<(long)M1 * DIM / 512, 256>>>(a, ah, al);
    {
        dim3 grid(DIM / 32, DIM / 32, 1);
        dim3 blk(32, 8, 1);
        wsplit_kernel<<<grid, blk>>>(w_q, wth + 0L * DIM * DIM, wtl + 0L * DIM * DIM);
        wsplit_kernel<<<grid, blk>>>(w_k, wth + 1L * DIM * DIM, wtl + 1L * DIM * DIM);
        wsplit_kernel<<<grid, blk>>>(w_v, wth + 2L * DIM * DIM, wtl + 2L * DIM * DIM);
    }

    // 1) projections -> hi/lo outputs
    {
        dim3 grid(DIM / BN, M1 / BM, 1);
        bf16x3_gemm<true, true><<<grid, GTHREADS, SMEM_SZ>>>(
            ah, al, wth + 0L * DIM * DIM, wtl + 0L * DIM * DIM, b_q,
            nullptr, qh, ql, M1, DIM, DIM, 0, 0, 0);
        bf16x3_gemm<true, true><<<grid, GTHREADS, SMEM_SZ>>>(
            ah, al, wth + 1L * DIM * DIM, wtl + 1L * DIM * DIM, b_k,
            nullptr, kh, kl, M1, DIM, DIM, 0, 0, 0);
        bf16x3_gemm<true, true><<<grid, GTHREADS, SMEM_SZ>>>(
            ah, al, wth + 2L * DIM * DIM, wtl + 2L * DIM * DIM, b_v,
            nullptr, vh, vl, M1, DIM, DIM, 0, 0, 0);
    }

    // 2) vt h/l = transpose(v h/l)
    {
        dim3 grid(DIM / 32, SEQ / 32, BATCH);
        dim3 blk(32, 8, 1);
        transpose_bf16<<<grid, blk>>>((const uint16_t*)vh, (uint16_t*)vth,
                                      SEQ, DIM, (long)SEQ * DIM, (long)DIM * SEQ);
        transpose_bf16<<<grid, blk>>>((const uint16_t*)vl, (uint16_t*)vtl,
                                      SEQ, DIM, (long)SEQ * DIM, (long)DIM * SEQ);
    }

    // 3) scores = q @ k^T (fp32 out)
    {
        dim3 grid(SEQ / BN, SEQ / BM, BATCH);
        bf16x3_gemm<false, false><<<grid, GTHREADS, SMEM_SZ>>>(
            qh, ql, kh, kl, nullptr, s, nullptr, nullptr,
            SEQ, SEQ, DIM, (long)SEQ * DIM, (long)SEQ * DIM, (long)SEQ * SEQ);
    }

    // 4) softmax -> p hi/lo
    softmax_split<<<BATCH * SEQ, 256>>>(s, ph, pl);

    // 5) out = p @ vt^T (fp32 out)
    {
        dim3 grid(DIM / BN, SEQ / BM, BATCH);
        bf16x3_gemm<false, false><<<grid, GTHREADS, SMEM_SZ>>>(
            ph, pl, vth, vtl, nullptr, out, nullptr, nullptr,
            SEQ, DIM, SEQ, (long)SEQ * SEQ, (long)DIM * SEQ, (long)SEQ * DIM);
    }
}

// round 11
// speedup vs baseline: 1.1221x; 1.1221x over previous
#include <cuda_runtime.h>
#include <cuda_fp16.h>
#include <cstdint>
#include <math.h>

// ---------------------------------------------------------------------------
// Self-attention B=4, S=2048, D=1024 — Round 10.
// R7 GEMM config (proven 1083us: 128x64 block, 4 warps 64x32, BKE=64,
// 2-stage cp.async, 2 CTAs/SM) with bf16 -> fp16 (same HMMA throughput,
// 11-bit mantissa):
//   - projections & scores: fp16 3-term split (error ~2^-22, better than bf16x3)
//   - P@V: P stored as SINGLE fp16 (no split) -> 2-term GEMM (-1/3 MMA work)
// ---------------------------------------------------------------------------

#define BATCH 4
#define SEQ   2048
#define DIM   1024

typedef __half f16;

// ---------------- scratch ---------------------------------------------------
__device__ f16   g_ah[BATCH * SEQ * DIM], g_al[BATCH * SEQ * DIM];
__device__ f16   g_wth[3 * DIM * DIM],    g_wtl[3 * DIM * DIM];
__device__ f16   g_qh[BATCH * SEQ * DIM], g_ql[BATCH * SEQ * DIM];
__device__ f16   g_kh[BATCH * SEQ * DIM], g_kl[BATCH * SEQ * DIM];
__device__ f16   g_vh[BATCH * SEQ * DIM], g_vl[BATCH * SEQ * DIM];
__device__ f16   g_vth[BATCH * DIM * SEQ], g_vtl[BATCH * DIM * SEQ];
__device__ float g_s [BATCH * SEQ * SEQ];
__device__ f16   g_ph[BATCH * SEQ * SEQ];          // P single fp16

// ---------------- helpers ---------------------------------------------------
__device__ __forceinline__ uint32_t smem_u32(const void* p) {
    uint32_t a;
    asm("{ .reg .u64 t; cvta.to.shared.u64 t, %1; cvt.u32.u64 %0, t; }"
        : "=r"(a) : "l"(p));
    return a;
}
__device__ __forceinline__ void cp16(uint32_t dst, const void* src) {
    asm volatile("cp.async.cg.shared.global [%0], [%1], 16;"
                 :: "r"(dst), "l"(src));
}
#define CP_COMMIT() asm volatile("cp.async.commit_group;" ::: "memory")
#define CP_WAIT(n)  asm volatile("cp.async.wait_group %0;" :: "n"(n) : "memory")

__device__ __forceinline__ void ldm_x4(uint32_t* r, uint32_t addr) {
    asm volatile("ldmatrix.sync.aligned.m8n8.x4.shared.b16 {%0,%1,%2,%3}, [%4];"
                 : "=r"(r[0]), "=r"(r[1]), "=r"(r[2]), "=r"(r[3]) : "r"(addr));
}
__device__ __forceinline__ void mma_f16(float* c, const uint32_t* a,
                                        const uint32_t* b) {
    asm volatile(
        "mma.sync.aligned.m16n8k16.row.col.f32.f16.f16.f32 "
        "{%0,%1,%2,%3}, {%4,%5,%6,%7}, {%8,%9}, {%0,%1,%2,%3};"
        : "+f"(c[0]), "+f"(c[1]), "+f"(c[2]), "+f"(c[3])
        : "r"(a[0]), "r"(a[1]), "r"(a[2]), "r"(a[3]), "r"(b[0]), "r"(b[1]));
}
__device__ __forceinline__ uint32_t hpack(f16 a, f16 b) {
    union { __half2 v; uint32_t u; } t;
    t.v = __halves2half2(a, b);
    return t.u;
}
// split two fp32 into packed hi / lo fp16x2 words
__device__ __forceinline__ void split2(float x, float y, uint32_t& hi,
                                       uint32_t& lo) {
    f16 hx = __float2half_rn(x), hy = __float2half_rn(y);
    hi = hpack(hx, hy);
    lo = hpack(__float2half_rn(x - __half2float(hx)),
               __float2half_rn(y - __half2float(hy)));
}

// ---------------- GEMM config ----------------------------------------------
#define BM 128
#define BN 64
#define BKE 64                 // fp16 elems per stage (4 x k16)
#define GTHREADS 128           // 4 warps: 2(M) x 2(N), warp tile 64x32

#define ROWB   144             // 128B data + 16B pad
#define AT_B   (128 * ROWB)
#define BT_B   (64 * ROWB)
#define ST_AHI 0
#define ST_ALO (AT_B)
#define ST_BHI (2 * AT_B)
#define ST_BLO (2 * AT_B + BT_B)
#define STAGEB (2 * AT_B + 2 * BT_B)        // 55296
#define SMEM_SZ (2 * STAGEB)                // 110592 -> 2 CTAs/SM

template<int R>
__device__ __forceinline__ void issue_tile(const f16* src, uint32_t dst,
                                           int K, long k0, int tid) {
#pragma unroll
    for (int it = 0; it < R * 8 / GTHREADS; it++) {
        int c = tid + it * GTHREADS;
        int row = c >> 3, col = c & 7;
        cp16(dst + row * ROWB + col * 16, src + (long)row * K + k0 + col * 8);
    }
}

// NT GEMM: C[m][n] = sum_k A[m][k]*B[n][k].
// A_SPLIT: A has hi/lo (3-term with B hi/lo); else A single (2-term).
template<bool HAS_BIAS, bool SPLIT_OUT, bool A_SPLIT>
__global__ void __launch_bounds__(GTHREADS, 2)
f16_gemm(const f16* __restrict__ Ah, const f16* __restrict__ Al,
         const f16* __restrict__ Bh, const f16* __restrict__ Bl,
         const float* __restrict__ bias,
         float* __restrict__ Cf, f16* __restrict__ Ch, f16* __restrict__ Cl,
         int M, int N, int K, long sA, long sB, long sC)
{
    extern __shared__ char smem[];
    const uint32_t sbase = smem_u32(smem);
    const int tid  = threadIdx.x;
    const int lane = tid & 31;
    const int wid  = tid >> 5;
    const int wm0  = (wid >> 1) * 64;
    const int wn0  = (wid & 1) * 32;
    const int m0 = blockIdx.y * BM;
    const int n0 = blockIdx.x * BN;

    const f16* Ahb = Ah + (long)blockIdx.z * sA + (long)m0 * K;
    const f16* Alb = A_SPLIT ? (Al + (long)blockIdx.z * sA + (long)m0 * K) : nullptr;
    const f16* Bhb = Bh + (long)blockIdx.z * sB + (long)n0 * K;
    const f16* Blb = Bl + (long)blockIdx.z * sB + (long)n0 * K;

    const uint32_t partA = (uint32_t)((wm0 + (lane & 15)) * ROWB
                                      + ((lane >> 4) << 4));
    const uint32_t partB = (uint32_t)((wn0 + (lane & 7) + ((lane >> 4) << 3)) * ROWB
                                      + ((lane & 8) ? 16 : 0));

    float acc[4][4][4];
#pragma unroll
    for (int i = 0; i < 4; i++)
#pragma unroll
        for (int j = 0; j < 4; j++)
#pragma unroll
            for (int r = 0; r < 4; r++) acc[i][j][r] = 0.f;

    const int NC = K / BKE;

    // prologue: stage 0
    issue_tile<128>(Ahb, sbase + ST_AHI, K, 0, tid);
    if (A_SPLIT) issue_tile<128>(Alb, sbase + ST_ALO, K, 0, tid);
    issue_tile<64> (Bhb, sbase + ST_BHI, K, 0, tid);
    issue_tile<64> (Blb, sbase + ST_BLO, K, 0, tid);
    CP_COMMIT();

    for (int i = 0; i < NC; i++) {
        __syncthreads();
        if (i + 1 < NC) {
            uint32_t sb = sbase + (uint32_t)(((i + 1) & 1) * STAGEB);
            long k0 = (long)(i + 1) * BKE;
            issue_tile<128>(Ahb, sb + ST_AHI, K, k0, tid);
            if (A_SPLIT) issue_tile<128>(Alb, sb + ST_ALO, K, k0, tid);
            issue_tile<64> (Bhb, sb + ST_BHI, K, k0, tid);
            issue_tile<64> (Blb, sb + ST_BLO, K, k0, tid);
            CP_COMMIT();
            CP_WAIT(1);
        } else {
            CP_WAIT(0);
        }
        __syncthreads();

        const uint32_t st = sbase + (uint32_t)((i & 1) * STAGEB);
#pragma unroll
        for (int ks = 0; ks < 4; ks++) {
            uint32_t ah[4][4], al[4][4], bh[4][2], bl[4][2];
#pragma unroll
            for (int mf = 0; mf < 4; mf++) {
                uint32_t off = (uint32_t)(mf * 16 * ROWB + ks * 32) + partA;
                ldm_x4(ah[mf], st + ST_AHI + off);
                if (A_SPLIT) ldm_x4(al[mf], st + ST_ALO + off);
            }
#pragma unroll
            for (int nf2 = 0; nf2 < 2; nf2++) {
                uint32_t off = (uint32_t)(nf2 * 16 * ROWB + ks * 32) + partB;
                uint32_t t[4];
                ldm_x4(t, st + ST_BHI + off);
                bh[nf2 * 2][0] = t[0]; bh[nf2 * 2][1] = t[1];
                bh[nf2 * 2 + 1][0] = t[2]; bh[nf2 * 2 + 1][1] = t[3];
                ldm_x4(t, st + ST_BLO + off);
                bl[nf2 * 2][0] = t[0]; bl[nf2 * 2][1] = t[1];
                bl[nf2 * 2 + 1][0] = t[2]; bl[nf2 * 2 + 1][1] = t[3];
            }
#pragma unroll
            for (int nf = 0; nf < 4; nf++)
#pragma unroll
                for (int mf = 0; mf < 4; mf++) {
                    mma_f16(acc[mf][nf], ah[mf], bh[nf]);        // hi*hi
                    mma_f16(acc[mf][nf], ah[mf], bl[nf]);        // hi*lo
                    if (A_SPLIT)
                        mma_f16(acc[mf][nf], al[mf], bh[nf]);    // lo*hi
                }
        }
    }

    // epilogue
    const int gid = lane >> 2, tig = lane & 3;
#pragma unroll
    for (int mf = 0; mf < 4; mf++) {
        int r0 = m0 + wm0 + mf * 16 + gid;
#pragma unroll
        for (int nf = 0; nf < 4; nf++) {
            int c0 = n0 + wn0 + nf * 8 + tig * 2;
            float bx = 0.f, by = 0.f;
            if (HAS_BIAS) { bx = bias[c0]; by = bias[c0 + 1]; }
            float x0 = acc[mf][nf][0] + bx, y0 = acc[mf][nf][1] + by;
            float x1 = acc[mf][nf][2] + bx, y1 = acc[mf][nf][3] + by;
            if (SPLIT_OUT) {
                long o0 = (long)(r0) * N + c0 + (long)blockIdx.z * sC;
                long o1 = (long)(r0 + 8) * N + c0 + (long)blockIdx.z * sC;
                uint32_t h, l;
                split2(x0, y0, h, l);
                *(uint32_t*)(Ch + o0) = h; *(uint32_t*)(Cl + o0) = l;
                split2(x1, y1, h, l);
                *(uint32_t*)(Ch + o1) = h; *(uint32_t*)(Cl + o1) = l;
            } else {
                float* Cb = Cf + (long)blockIdx.z * sC;
                *(float2*)(Cb + (long)r0 * N + c0) = make_float2(x0, y0);
                *(float2*)(Cb + (long)(r0 + 8) * N + c0) = make_float2(x1, y1);
            }
        }
    }
}

// ---------------- split a ---------------------------------------------------
__global__ void __launch_bounds__(256)
split_kernel(const float* __restrict__ src, f16* __restrict__ h,
             f16* __restrict__ l)
{
    long idx = (long)blockIdx.x * 256 + threadIdx.x;
    float2 v = ((const float2*)src)[idx];
    uint32_t hw, lw;
    split2(v.x, v.y, hw, lw);
    ((uint32_t*)h)[idx] = hw;
    ((uint32_t*)l)[idx] = lw;
}

// ---------------- weight transpose + split ----------------------------------
__global__ void __launch_bounds__(256)
wsplit_kernel(const float* __restrict__ w, f16* __restrict__ h,
              f16* __restrict__ l)
{
    __shared__ float t[32][33];
    int x = blockIdx.x * 32 + threadIdx.x;
    int y = blockIdx.y * 32 + threadIdx.y;
#pragma unroll
    for (int j = 0; j < 32; j += 8)
        t[threadIdx.y + j][threadIdx.x] = w[(long)(y + j) * DIM + x];
    __syncthreads();
    x = blockIdx.y * 32 + threadIdx.x;
    y = blockIdx.x * 32 + threadIdx.y;
#pragma unroll
    for (int j = 0; j < 32; j += 8) {
        float v = t[threadIdx.x][threadIdx.y + j];
        f16 hv = __float2half_rn(v);
        h[(long)(y + j) * DIM + x] = hv;
        l[(long)(y + j) * DIM + x] =
            __float2half_rn(v - __half2float(hv));
    }
}

// ---------------- f16 transpose ---------------------------------------------
__global__ void __launch_bounds__(256)
transpose_f16(const uint16_t* __restrict__ src, uint16_t* __restrict__ dst,
              int R, int C, long sS, long sD)
{
    __shared__ uint16_t t[32][33];
    src += (long)blockIdx.z * sS;
    dst += (long)blockIdx.z * sD;
    int x = blockIdx.x * 32 + threadIdx.x;
    int y = blockIdx.y * 32 + threadIdx.y;
#pragma unroll
    for (int j = 0; j < 32; j += 8)
        t[threadIdx.y + j][threadIdx.x] = src[(long)(y + j) * C + x];
    __syncthreads();
    x = blockIdx.y * 32 + threadIdx.x;
    y = blockIdx.x * 32 + threadIdx.y;
#pragma unroll
    for (int j = 0; j < 32; j += 8)
        dst[(long)(y + j) * R + x] = t[threadIdx.x][threadIdx.y + j];
}

// ---------------- softmax -> single fp16 P ----------------------------------
__global__ void __launch_bounds__(256)
softmax_f16(const float* __restrict__ S, f16* __restrict__ Ph)
{
    const float2* row = (const float2*)(S + (long)blockIdx.x * SEQ);
    uint32_t* oh = (uint32_t*)(Ph + (long)blockIdx.x * SEQ);
    __shared__ float red[256];
    const int tid = threadIdx.x;

    float2 e[4];
#pragma unroll
    for (int j = 0; j < 4; j++) e[j] = row[tid + j * 256];

    float m = -INFINITY;
#pragma unroll
    for (int j = 0; j < 4; j++) m = fmaxf(m, fmaxf(e[j].x, e[j].y));
    red[tid] = m;
    __syncthreads();
    for (int s = 128; s > 0; s >>= 1) {
        if (tid < s) red[tid] = fmaxf(red[tid], red[tid + s]);
        __syncthreads();
    }
    m = red[0];
    __syncthreads();

    float sum = 0.f;
#pragma unroll
    for (int j = 0; j < 4; j++) {
        e[j].x = __expf(e[j].x - m);
        e[j].y = __expf(e[j].y - m);
        sum += e[j].x + e[j].y;
    }
    red[tid] = sum;
    __syncthreads();
    for (int s = 128; s > 0; s >>= 1) {
        if (tid < s) red[tid] += red[tid + s];
        __syncthreads();
    }
    float inv = 1.f / red[0];

#pragma unroll
    for (int j = 0; j < 4; j++)
        oh[tid + j * 256] = hpack(__float2half_rn(e[j].x * inv),
                                  __float2half_rn(e[j].y * inv));
}

// ---------------------------------------------------------------------------
extern "C" void kernel_launch(void* const* d_in, const int* in_sizes, int n_in,
                              void* d_out, int out_size)
{
    const float* a   = (const float*)d_in[0];
    const float* w_q = (const float*)d_in[1];
    const float* b_q = (const float*)d_in[2];
    const float* w_k = (const float*)d_in[3];
    const float* b_k = (const float*)d_in[4];
    const float* w_v = (const float*)d_in[5];
    const float* b_v = (const float*)d_in[6];
    float* out = (float*)d_out;

    f16 *ah, *al, *wth, *wtl, *qh, *ql, *kh, *kl, *vh, *vl, *vth, *vtl, *ph;
    float* s;
    cudaGetSymbolAddress((void**)&ah,  g_ah);  cudaGetSymbolAddress((void**)&al,  g_al);
    cudaGetSymbolAddress((void**)&wth, g_wth); cudaGetSymbolAddress((void**)&wtl, g_wtl);
    cudaGetSymbolAddress((void**)&qh,  g_qh);  cudaGetSymbolAddress((void**)&ql,  g_ql);
    cudaGetSymbolAddress((void**)&kh,  g_kh);  cudaGetSymbolAddress((void**)&kl,  g_kl);
    cudaGetSymbolAddress((void**)&vh,  g_vh);  cudaGetSymbolAddress((void**)&vl,  g_vl);
    cudaGetSymbolAddress((void**)&vth, g_vth); cudaGetSymbolAddress((void**)&vtl, g_vtl);
    cudaGetSymbolAddress((void**)&ph,  g_ph);
    cudaGetSymbolAddress((void**)&s,   g_s);

    cudaFuncSetAttribute(f16_gemm<true, true, true>,
                         cudaFuncAttributeMaxDynamicSharedMemorySize, SMEM_SZ);
    cudaFuncSetAttribute(f16_gemm<false, false, true>,
                         cudaFuncAttributeMaxDynamicSharedMemorySize, SMEM_SZ);
    cudaFuncSetAttribute(f16_gemm<false, false, false>,
                         cudaFuncAttributeMaxDynamicSharedMemorySize, SMEM_SZ);

    const int M1 = BATCH * SEQ;   // 8192

    // 0) operand prep
    split_kernel<<<(long)M1 * DIM / 512, 256>>>(a, ah, al);
    {
        dim3 grid(DIM / 32, DIM / 32, 1);
        dim3 blk(32, 8, 1);
        wsplit_kernel<<<grid, blk>>>(w_q, wth + 0L * DIM * DIM, wtl + 0L * DIM * DIM);
        wsplit_kernel<<<grid, blk>>>(w_k, wth + 1L * DIM * DIM, wtl + 1L * DIM * DIM);
        wsplit_kernel<<<grid, blk>>>(w_v, wth + 2L * DIM * DIM, wtl + 2L * DIM * DIM);
    }

    // 1) projections -> hi/lo outputs
    {
        dim3 grid(DIM / BN, M1 / BM, 1);
        f16_gemm<true, true, true><<<grid, GTHREADS, SMEM_SZ>>>(
            ah, al, wth + 0L * DIM * DIM, wtl + 0L * DIM * DIM, b_q,
            nullptr, qh, ql, M1, DIM, DIM, 0, 0, 0);
        f16_gemm<true, true, true><<<grid, GTHREADS, SMEM_SZ>>>(
            ah, al, wth + 1L * DIM * DIM, wtl + 1L * DIM * DIM, b_k,
            nullptr, kh, kl, M1, DIM, DIM, 0, 0, 0);
        f16_gemm<true, true, true><<<grid, GTHREADS, SMEM_SZ>>>(
            ah, al, wth + 2L * DIM * DIM, wtl + 2L * DIM * DIM, b_v,
            nullptr, vh, vl, M1, DIM, DIM, 0, 0, 0);
    }

    // 2) vt h/l = transpose(v h/l)
    {
        dim3 grid(DIM / 32, SEQ / 32, BATCH);
        dim3 blk(32, 8, 1);
        transpose_f16<<<grid, blk>>>((const uint16_t*)vh, (uint16_t*)vth,
                                     SEQ, DIM, (long)SEQ * DIM, (long)DIM * SEQ);
        transpose_f16<<<grid, blk>>>((const uint16_t*)vl, (uint16_t*)vtl,
                                     SEQ, DIM, (long)SEQ * DIM, (long)DIM * SEQ);
    }

    // 3) scores = q @ k^T (fp32 out, 3-term)
    {
        dim3 grid(SEQ / BN, SEQ / BM, BATCH);
        f16_gemm<false, false, true><<<grid, GTHREADS, SMEM_SZ>>>(
            qh, ql, kh, kl, nullptr, s, nullptr, nullptr,
            SEQ, SEQ, DIM, (long)SEQ * DIM, (long)SEQ * DIM, (long)SEQ * SEQ);
    }

    // 4) softmax -> single fp16 P
    softmax_f16<<<BATCH * SEQ, 256>>>(s, ph);

    // 5) out = P @ vt^T (fp32 out, 2-term: P x (Vh+Vl))
    {
        dim3 grid(DIM / BN, SEQ / BM, BATCH);
        f16_gemm<false, false, false><<<grid, GTHREADS, SMEM_SZ>>>(
            ph, nullptr, vth, vtl, nullptr, out, nullptr, nullptr,
            SEQ, DIM, SEQ, (long)SEQ * SEQ, (long)DIM * SEQ, (long)SEQ * DIM);
    }
}

// round 12
// speedup vs baseline: 1.2251x; 1.0918x over previous
#include <cuda_runtime.h>
#include <cuda_fp16.h>
#include <cstdint>
#include <math.h>

// ---------------------------------------------------------------------------
// Self-attention B=4, S=2048, D=1024 — Round 11.
// fp16 split GEMMs on mma.sync.m16n8k16, R7-proven shape (128x64 block,
// 4 warps 64x32, BKE=64, 2-stage cp.async, 2 CTAs/SM).
// Precision budget (calibrated: each dropped 2^-11 factor term ~ +1.4e-4):
//   - projections Q,K: 3-term, split fp16 out
//   - projection  V:   3-term, SINGLE fp16 out (V_lo dropped)
//   - scores:          3-term, fp32 out
//   - P@V:             1-term (P single x Vh single)
// ---------------------------------------------------------------------------

#define BATCH 4
#define SEQ   2048
#define DIM   1024

typedef __half f16;

// ---------------- scratch ---------------------------------------------------
__device__ f16   g_ah[BATCH * SEQ * DIM], g_al[BATCH * SEQ * DIM];
__device__ f16   g_wth[3 * DIM * DIM],    g_wtl[3 * DIM * DIM];
__device__ f16   g_qh[BATCH * SEQ * DIM], g_ql[BATCH * SEQ * DIM];
__device__ f16   g_kh[BATCH * SEQ * DIM], g_kl[BATCH * SEQ * DIM];
__device__ f16   g_vh[BATCH * SEQ * DIM];
__device__ f16   g_vth[BATCH * DIM * SEQ];
__device__ float g_s [BATCH * SEQ * SEQ];
__device__ f16   g_ph[BATCH * SEQ * SEQ];          // P single fp16

// ---------------- helpers ---------------------------------------------------
__device__ __forceinline__ uint32_t smem_u32(const void* p) {
    uint32_t a;
    asm("{ .reg .u64 t; cvta.to.shared.u64 t, %1; cvt.u32.u64 %0, t; }"
        : "=r"(a) : "l"(p));
    return a;
}
__device__ __forceinline__ void cp16(uint32_t dst, const void* src) {
    asm volatile("cp.async.cg.shared.global [%0], [%1], 16;"
                 :: "r"(dst), "l"(src));
}
#define CP_COMMIT() asm volatile("cp.async.commit_group;" ::: "memory")
#define CP_WAIT(n)  asm volatile("cp.async.wait_group %0;" :: "n"(n) : "memory")

__device__ __forceinline__ void ldm_x4(uint32_t* r, uint32_t addr) {
    asm volatile("ldmatrix.sync.aligned.m8n8.x4.shared.b16 {%0,%1,%2,%3}, [%4];"
                 : "=r"(r[0]), "=r"(r[1]), "=r"(r[2]), "=r"(r[3]) : "r"(addr));
}
__device__ __forceinline__ void mma_f16(float* c, const uint32_t* a,
                                        const uint32_t* b) {
    asm volatile(
        "mma.sync.aligned.m16n8k16.row.col.f32.f16.f16.f32 "
        "{%0,%1,%2,%3}, {%4,%5,%6,%7}, {%8,%9}, {%0,%1,%2,%3};"
        : "+f"(c[0]), "+f"(c[1]), "+f"(c[2]), "+f"(c[3])
        : "r"(a[0]), "r"(a[1]), "r"(a[2]), "r"(a[3]), "r"(b[0]), "r"(b[1]));
}
__device__ __forceinline__ uint32_t hpack(f16 a, f16 b) {
    union { __half2 v; uint32_t u; } t;
    t.v = __halves2half2(a, b);
    return t.u;
}
__device__ __forceinline__ void split2(float x, float y, uint32_t& hi,
                                       uint32_t& lo) {
    f16 hx = __float2half_rn(x), hy = __float2half_rn(y);
    hi = hpack(hx, hy);
    lo = hpack(__float2half_rn(x - __half2float(hx)),
               __float2half_rn(y - __half2float(hy)));
}

// ---------------- GEMM config ----------------------------------------------
#define BM 128
#define BN 64
#define BKE 64                 // fp16 elems per stage (4 x k16)
#define GTHREADS 128           // 4 warps: 2(M) x 2(N), warp tile 64x32

#define ROWB   144             // 128B data + 16B pad
#define AT_B   (128 * ROWB)
#define BT_B   (64 * ROWB)
#define ST_AHI 0
#define ST_ALO (AT_B)
#define ST_BHI (2 * AT_B)
#define ST_BLO (2 * AT_B + BT_B)
#define STAGEB (2 * AT_B + 2 * BT_B)        // 55296
#define SMEM_SZ (2 * STAGEB)                // 110592 -> 2 CTAs/SM

// output modes
#define OUT_F32   0
#define OUT_SPLIT 1
#define OUT_HALF  2

template<int R>
__device__ __forceinline__ void issue_tile(const f16* src, uint32_t dst,
                                           int K, long k0, int tid) {
#pragma unroll
    for (int it = 0; it < R * 8 / GTHREADS; it++) {
        int c = tid + it * GTHREADS;
        int row = c >> 3, col = c & 7;
        cp16(dst + row * ROWB + col * 16, src + (long)row * K + k0 + col * 8);
    }
}

// NT GEMM: C[m][n] = sum_k A[m][k]*B[n][k].
// Terms: hi*hi  (+ hi*lo if B_SPLIT)  (+ lo*hi if A_SPLIT)
template<int OUT_MODE, bool A_SPLIT, bool B_SPLIT, bool HAS_BIAS>
__global__ void __launch_bounds__(GTHREADS, 2)
f16_gemm(const f16* __restrict__ Ah, const f16* __restrict__ Al,
         const f16* __restrict__ Bh, const f16* __restrict__ Bl,
         const float* __restrict__ bias,
         float* __restrict__ Cf, f16* __restrict__ Ch, f16* __restrict__ Cl,
         int M, int N, int K, long sA, long sB, long sC)
{
    extern __shared__ char smem[];
    const uint32_t sbase = smem_u32(smem);
    const int tid  = threadIdx.x;
    const int lane = tid & 31;
    const int wid  = tid >> 5;
    const int wm0  = (wid >> 1) * 64;
    const int wn0  = (wid & 1) * 32;
    const int m0 = blockIdx.y * BM;
    const int n0 = blockIdx.x * BN;

    const f16* Ahb = Ah + (long)blockIdx.z * sA + (long)m0 * K;
    const f16* Alb = A_SPLIT ? (Al + (long)blockIdx.z * sA + (long)m0 * K) : nullptr;
    const f16* Bhb = Bh + (long)blockIdx.z * sB + (long)n0 * K;
    const f16* Blb = B_SPLIT ? (Bl + (long)blockIdx.z * sB + (long)n0 * K) : nullptr;

    const uint32_t partA = (uint32_t)((wm0 + (lane & 15)) * ROWB
                                      + ((lane >> 4) << 4));
    const uint32_t partB = (uint32_t)((wn0 + (lane & 7) + ((lane >> 4) << 3)) * ROWB
                                      + ((lane & 8) ? 16 : 0));

    float acc[4][4][4];
#pragma unroll
    for (int i = 0; i < 4; i++)
#pragma unroll
        for (int j = 0; j < 4; j++)
#pragma unroll
            for (int r = 0; r < 4; r++) acc[i][j][r] = 0.f;

    const int NC = K / BKE;

    // prologue: stage 0
    issue_tile<128>(Ahb, sbase + ST_AHI, K, 0, tid);
    if (A_SPLIT) issue_tile<128>(Alb, sbase + ST_ALO, K, 0, tid);
    issue_tile<64> (Bhb, sbase + ST_BHI, K, 0, tid);
    if (B_SPLIT) issue_tile<64> (Blb, sbase + ST_BLO, K, 0, tid);
    CP_COMMIT();

    for (int i = 0; i < NC; i++) {
        __syncthreads();
        if (i + 1 < NC) {
            uint32_t sb = sbase + (uint32_t)(((i + 1) & 1) * STAGEB);
            long k0 = (long)(i + 1) * BKE;
            issue_tile<128>(Ahb, sb + ST_AHI, K, k0, tid);
            if (A_SPLIT) issue_tile<128>(Alb, sb + ST_ALO, K, k0, tid);
            issue_tile<64> (Bhb, sb + ST_BHI, K, k0, tid);
            if (B_SPLIT) issue_tile<64> (Blb, sb + ST_BLO, K, k0, tid);
            CP_COMMIT();
            CP_WAIT(1);
        } else {
            CP_WAIT(0);
        }
        __syncthreads();

        const uint32_t st = sbase + (uint32_t)((i & 1) * STAGEB);
#pragma unroll
        for (int ks = 0; ks < 4; ks++) {
            uint32_t ah[4][4], al[4][4], bh[4][2], bl[4][2];
#pragma unroll
            for (int mf = 0; mf < 4; mf++) {
                uint32_t off = (uint32_t)(mf * 16 * ROWB + ks * 32) + partA;
                ldm_x4(ah[mf], st + ST_AHI + off);
                if (A_SPLIT) ldm_x4(al[mf], st + ST_ALO + off);
            }
#pragma unroll
            for (int nf2 = 0; nf2 < 2; nf2++) {
                uint32_t off = (uint32_t)(nf2 * 16 * ROWB + ks * 32) + partB;
                uint32_t t[4];
                ldm_x4(t, st + ST_BHI + off);
                bh[nf2 * 2][0] = t[0]; bh[nf2 * 2][1] = t[1];
                bh[nf2 * 2 + 1][0] = t[2]; bh[nf2 * 2 + 1][1] = t[3];
                if (B_SPLIT) {
                    ldm_x4(t, st + ST_BLO + off);
                    bl[nf2 * 2][0] = t[0]; bl[nf2 * 2][1] = t[1];
                    bl[nf2 * 2 + 1][0] = t[2]; bl[nf2 * 2 + 1][1] = t[3];
                }
            }
#pragma unroll
            for (int nf = 0; nf < 4; nf++)
#pragma unroll
                for (int mf = 0; mf < 4; mf++) {
                    mma_f16(acc[mf][nf], ah[mf], bh[nf]);          // hi*hi
                    if (B_SPLIT) mma_f16(acc[mf][nf], ah[mf], bl[nf]); // hi*lo
                    if (A_SPLIT) mma_f16(acc[mf][nf], al[mf], bh[nf]); // lo*hi
                }
        }
    }

    // epilogue
    const int gid = lane >> 2, tig = lane & 3;
#pragma unroll
    for (int mf = 0; mf < 4; mf++) {
        int r0 = m0 + wm0 + mf * 16 + gid;
#pragma unroll
        for (int nf = 0; nf < 4; nf++) {
            int c0 = n0 + wn0 + nf * 8 + tig * 2;
            float bx = 0.f, by = 0.f;
            if (HAS_BIAS) { bx = bias[c0]; by = bias[c0 + 1]; }
            float x0 = acc[mf][nf][0] + bx, y0 = acc[mf][nf][1] + by;
            float x1 = acc[mf][nf][2] + bx, y1 = acc[mf][nf][3] + by;
            long o0 = (long)(r0) * N + c0 + (long)blockIdx.z * sC;
            long o1 = (long)(r0 + 8) * N + c0 + (long)blockIdx.z * sC;
            if (OUT_MODE == OUT_SPLIT) {
                uint32_t h, l;
                split2(x0, y0, h, l);
                *(uint32_t*)(Ch + o0) = h; *(uint32_t*)(Cl + o0) = l;
                split2(x1, y1, h, l);
                *(uint32_t*)(Ch + o1) = h; *(uint32_t*)(Cl + o1) = l;
            } else if (OUT_MODE == OUT_HALF) {
                *(uint32_t*)(Ch + o0) =
                    hpack(__float2half_rn(x0), __float2half_rn(y0));
                *(uint32_t*)(Ch + o1) =
                    hpack(__float2half_rn(x1), __float2half_rn(y1));
            } else {
                float* Cb = Cf + (long)blockIdx.z * sC;
                *(float2*)(Cb + (long)r0 * N + c0) = make_float2(x0, y0);
                *(float2*)(Cb + (long)(r0 + 8) * N + c0) = make_float2(x1, y1);
            }
        }
    }
}

// ---------------- split a ---------------------------------------------------
__global__ void __launch_bounds__(256)
split_kernel(const float* __restrict__ src, f16* __restrict__ h,
             f16* __restrict__ l)
{
    long idx = (long)blockIdx.x * 256 + threadIdx.x;
    float2 v = ((const float2*)src)[idx];
    uint32_t hw, lw;
    split2(v.x, v.y, hw, lw);
    ((uint32_t*)h)[idx] = hw;
    ((uint32_t*)l)[idx] = lw;
}

// ---------------- weight transpose + split ----------------------------------
__global__ void __launch_bounds__(256)
wsplit_kernel(const float* __restrict__ w, f16* __restrict__ h,
              f16* __restrict__ l)
{
    __shared__ float t[32][33];
    int x = blockIdx.x * 32 + threadIdx.x;
    int y = blockIdx.y * 32 + threadIdx.y;
#pragma unroll
    for (int j = 0; j < 32; j += 8)
        t[threadIdx.y + j][threadIdx.x] = w[(long)(y + j) * DIM + x];
    __syncthreads();
    x = blockIdx.y * 32 + threadIdx.x;
    y = blockIdx.x * 32 + threadIdx.y;
#pragma unroll
    for (int j = 0; j < 32; j += 8) {
        float v = t[threadIdx.x][threadIdx.y + j];
        f16 hv = __float2half_rn(v);
        h[(long)(y + j) * DIM + x] = hv;
        l[(long)(y + j) * DIM + x] =
            __float2half_rn(v - __half2float(hv));
    }
}

// ---------------- f16 transpose ---------------------------------------------
__global__ void __launch_bounds__(256)
transpose_f16(const uint16_t* __restrict__ src, uint16_t* __restrict__ dst,
              int R, int C, long sS, long sD)
{
    __shared__ uint16_t t[32][33];
    src += (long)blockIdx.z * sS;
    dst += (long)blockIdx.z * sD;
    int x = blockIdx.x * 32 + threadIdx.x;
    int y = blockIdx.y * 32 + threadIdx.y;
#pragma unroll
    for (int j = 0; j < 32; j += 8)
        t[threadIdx.y + j][threadIdx.x] = src[(long)(y + j) * C + x];
    __syncthreads();
    x = blockIdx.y * 32 + threadIdx.x;
    y = blockIdx.x * 32 + threadIdx.y;
#pragma unroll
    for (int j = 0; j < 32; j += 8)
        dst[(long)(y + j) * R + x] = t[threadIdx.x][threadIdx.y + j];
}

// ---------------- softmax -> single fp16 P ----------------------------------
__global__ void __launch_bounds__(256)
softmax_f16(const float* __restrict__ S, f16* __restrict__ Ph)
{
    const float2* row = (const float2*)(S + (long)blockIdx.x * SEQ);
    uint32_t* oh = (uint32_t*)(Ph + (long)blockIdx.x * SEQ);
    __shared__ float red[256];
    const int tid = threadIdx.x;

    float2 e[4];
#pragma unroll
    for (int j = 0; j < 4; j++) e[j] = row[tid + j * 256];

    float m = -INFINITY;
#pragma unroll
    for (int j = 0; j < 4; j++) m = fmaxf(m, fmaxf(e[j].x, e[j].y));
    red[tid] = m;
    __syncthreads();
    for (int s = 128; s > 0; s >>= 1) {
        if (tid < s) red[tid] = fmaxf(red[tid], red[tid + s]);
        __syncthreads();
    }
    m = red[0];
    __syncthreads();

    float sum = 0.f;
#pragma unroll
    for (int j = 0; j < 4; j++) {
        e[j].x = __expf(e[j].x - m);
        e[j].y = __expf(e[j].y - m);
        sum += e[j].x + e[j].y;
    }
    red[tid] = sum;
    __syncthreads();
    for (int s = 128; s > 0; s >>= 1) {
        if (tid < s) red[tid] += red[tid + s];
        __syncthreads();
    }
    float inv = 1.f / red[0];

#pragma unroll
    for (int j = 0; j < 4; j++)
        oh[tid + j * 256] = hpack(__float2half_rn(e[j].x * inv),
                                  __float2half_rn(e[j].y * inv));
}

// ---------------------------------------------------------------------------
extern "C" void kernel_launch(void* const* d_in, const int* in_sizes, int n_in,
                              void* d_out, int out_size)
{
    const float* a   = (const float*)d_in[0];
    const float* w_q = (const float*)d_in[1];
    const float* b_q = (const float*)d_in[2];
    const float* w_k = (const float*)d_in[3];
    const float* b_k = (const float*)d_in[4];
    const float* w_v = (const float*)d_in[5];
    const float* b_v = (const float*)d_in[6];
    float* out = (float*)d_out;

    f16 *ah, *al, *wth, *wtl, *qh, *ql, *kh, *kl, *vh, *vth, *ph;
    float* s;
    cudaGetSymbolAddress((void**)&ah,  g_ah);  cudaGetSymbolAddress((void**)&al,  g_al);
    cudaGetSymbolAddress((void**)&wth, g_wth); cudaGetSymbolAddress((void**)&wtl, g_wtl);
    cudaGetSymbolAddress((void**)&qh,  g_qh);  cudaGetSymbolAddress((void**)&ql,  g_ql);
    cudaGetSymbolAddress((void**)&kh,  g_kh);  cudaGetSymbolAddress((void**)&kl,  g_kl);
    cudaGetSymbolAddress((void**)&vh,  g_vh);  cudaGetSymbolAddress((void**)&vth, g_vth);
    cudaGetSymbolAddress((void**)&ph,  g_ph);
    cudaGetSymbolAddress((void**)&s,   g_s);

    cudaFuncSetAttribute(f16_gemm<OUT_SPLIT, true, true, true>,
                         cudaFuncAttributeMaxDynamicSharedMemorySize, SMEM_SZ);
    cudaFuncSetAttribute(f16_gemm<OUT_HALF, true, true, true>,
                         cudaFuncAttributeMaxDynamicSharedMemorySize, SMEM_SZ);
    cudaFuncSetAttribute(f16_gemm<OUT_F32, true, true, false>,
                         cudaFuncAttributeMaxDynamicSharedMemorySize, SMEM_SZ);
    cudaFuncSetAttribute(f16_gemm<OUT_F32, false, false, false>,
                         cudaFuncAttributeMaxDynamicSharedMemorySize, SMEM_SZ);

    const int M1 = BATCH * SEQ;   // 8192

    // 0) operand prep
    split_kernel<<<(long)M1 * DIM / 512, 256>>>(a, ah, al);
    {
        dim3 grid(DIM / 32, DIM / 32, 1);
        dim3 blk(32, 8, 1);
        wsplit_kernel<<<grid, blk>>>(w_q, wth + 0L * DIM * DIM, wtl + 0L * DIM * DIM);
        wsplit_kernel<<<grid, blk>>>(w_k, wth + 1L * DIM * DIM, wtl + 1L * DIM * DIM);
        wsplit_kernel<<<grid, blk>>>(w_v, wth + 2L * DIM * DIM, wtl + 2L * DIM * DIM);
    }

    // 1) projections: Q,K split out; V single fp16 out
    {
        dim3 grid(DIM / BN, M1 / BM, 1);
        f16_gemm<OUT_SPLIT, true, true, true><<<grid, GTHREADS, SMEM_SZ>>>(
            ah, al, wth + 0L * DIM * DIM, wtl + 0L * DIM * DIM, b_q,
            nullptr, qh, ql, M1, DIM, DIM, 0, 0, 0);
        f16_gemm<OUT_SPLIT, true, true, true><<<grid, GTHREADS, SMEM_SZ>>>(
            ah, al, wth + 1L * DIM * DIM, wtl + 1L * DIM * DIM, b_k,
            nullptr, kh, kl, M1, DIM, DIM, 0, 0, 0);
        f16_gemm<OUT_HALF, true, true, true><<<grid, GTHREADS, SMEM_SZ>>>(
            ah, al, wth + 2L * DIM * DIM, wtl + 2L * DIM * DIM, b_v,
            nullptr, vh, nullptr, M1, DIM, DIM, 0, 0, 0);
    }

    // 2) vt = transpose(vh)
    {
        dim3 grid(DIM / 32, SEQ / 32, BATCH);
        dim3 blk(32, 8, 1);
        transpose_f16<<<grid, blk>>>((const uint16_t*)vh, (uint16_t*)vth,
                                     SEQ, DIM, (long)SEQ * DIM, (long)DIM * SEQ);
    }

    // 3) scores = q @ k^T (fp32 out, 3-term)
    {
        dim3 grid(SEQ / BN, SEQ / BM, BATCH);
        f16_gemm<OUT_F32, true, true, false><<<grid, GTHREADS, SMEM_SZ>>>(
            qh, ql, kh, kl, nullptr, s, nullptr, nullptr,
            SEQ, SEQ, DIM, (long)SEQ * DIM, (long)SEQ * DIM, (long)SEQ * SEQ);
    }

    // 4) softmax -> single fp16 P
    softmax_f16<<<BATCH * SEQ, 256>>>(s, ph);

    // 5) out = P @ vt^T (fp32 out, 1-term)
    {
        dim3 grid(DIM / BN, SEQ / BM, BATCH);
        f16_gemm<OUT_F32, false, false, false><<<grid, GTHREADS, SMEM_SZ>>>(
            ph, nullptr, vth, nullptr, nullptr, out, nullptr, nullptr,
            SEQ, DIM, SEQ, (long)SEQ * SEQ, (long)DIM * SEQ, (long)SEQ * DIM);
    }
}

// round 13
// speedup vs baseline: 1.2901x; 1.0530x over previous
#include <cuda_runtime.h>
#include <cuda_fp16.h>
#include <cstdint>
#include <math.h>

// ---------------------------------------------------------------------------
// Self-attention B=4, S=2048, D=1024 — Round 12.
// fp16 split GEMMs (mma.sync.m16n8k16), R7-proven shape (128x64 block,
// 4 warps 64x32, BKE=64, 2-stage cp.async, 2 CTAs/SM).
// NEW: Q/K/V projections merged into ONE launch (gridDim.z=3: z selects
// weights/bias/output slab; shared A) -> kills 2 wave-quantization tails.
// Precision layout (calibrated):
//   Q,K: 3-term, split out | V: 3-term, hi used (lo written, unused)
//   scores: 3-term fp32    | P@V: 1-term (P f16 x Vh)
// ---------------------------------------------------------------------------

#define BATCH 4
#define SEQ   2048
#define DIM   1024

typedef __half f16;

#define M1 (BATCH * SEQ)            // 8192
#define PSL ((long)M1 * DIM)        // projection slab elements

// ---------------- scratch ---------------------------------------------------
__device__ f16   g_ah[PSL], g_al[PSL];
__device__ f16   g_wth[3 * DIM * DIM], g_wtl[3 * DIM * DIM];
__device__ f16   g_qkvh[3 * PSL], g_qkvl[3 * PSL];   // z slabs: q,k,v
__device__ f16   g_vth[BATCH * DIM * SEQ];
__device__ float g_s [BATCH * SEQ * SEQ];
__device__ f16   g_ph[BATCH * SEQ * SEQ];

// ---------------- helpers ---------------------------------------------------
__device__ __forceinline__ uint32_t smem_u32(const void* p) {
    uint32_t a;
    asm("{ .reg .u64 t; cvta.to.shared.u64 t, %1; cvt.u32.u64 %0, t; }"
        : "=r"(a) : "l"(p));
    return a;
}
__device__ __forceinline__ void cp16(uint32_t dst, const void* src) {
    asm volatile("cp.async.cg.shared.global [%0], [%1], 16;"
                 :: "r"(dst), "l"(src));
}
#define CP_COMMIT() asm volatile("cp.async.commit_group;" ::: "memory")
#define CP_WAIT(n)  asm volatile("cp.async.wait_group %0;" :: "n"(n) : "memory")

__device__ __forceinline__ void ldm_x4(uint32_t* r, uint32_t addr) {
    asm volatile("ldmatrix.sync.aligned.m8n8.x4.shared.b16 {%0,%1,%2,%3}, [%4];"
                 : "=r"(r[0]), "=r"(r[1]), "=r"(r[2]), "=r"(r[3]) : "r"(addr));
}
__device__ __forceinline__ void mma_f16(float* c, const uint32_t* a,
                                        const uint32_t* b) {
    asm volatile(
        "mma.sync.aligned.m16n8k16.row.col.f32.f16.f16.f32 "
        "{%0,%1,%2,%3}, {%4,%5,%6,%7}, {%8,%9}, {%0,%1,%2,%3};"
        : "+f"(c[0]), "+f"(c[1]), "+f"(c[2]), "+f"(c[3])
        : "r"(a[0]), "r"(a[1]), "r"(a[2]), "r"(a[3]), "r"(b[0]), "r"(b[1]));
}
__device__ __forceinline__ uint32_t hpack(f16 a, f16 b) {
    union { __half2 v; uint32_t u; } t;
    t.v = __halves2half2(a, b);
    return t.u;
}
__device__ __forceinline__ void split2(float x, float y, uint32_t& hi,
                                       uint32_t& lo) {
    f16 hx = __float2half_rn(x), hy = __float2half_rn(y);
    hi = hpack(hx, hy);
    lo = hpack(__float2half_rn(x - __half2float(hx)),
               __float2half_rn(y - __half2float(hy)));
}

// ---------------- GEMM config ----------------------------------------------
#define BM 128
#define BN 64
#define BKE 64
#define GTHREADS 128           // 4 warps: 2(M) x 2(N), warp tile 64x32

#define ROWB   144             // 128B data + 16B pad
#define AT_B   (128 * ROWB)
#define BT_B   (64 * ROWB)
#define ST_AHI 0
#define ST_ALO (AT_B)
#define ST_BHI (2 * AT_B)
#define ST_BLO (2 * AT_B + BT_B)
#define STAGEB (2 * AT_B + 2 * BT_B)        // 55296
#define SMEM_SZ (2 * STAGEB)                // 110592 -> 2 CTAs/SM

#define OUT_F32   0
#define OUT_SPLIT 1

template<int R>
__device__ __forceinline__ void issue_tile(const f16* src, uint32_t dst,
                                           int K, long k0, int tid) {
#pragma unroll
    for (int it = 0; it < R * 8 / GTHREADS; it++) {
        int c = tid + it * GTHREADS;
        int row = c >> 3, col = c & 7;
        cp16(dst + row * ROWB + col * 16, src + (long)row * K + k0 + col * 8);
    }
}

// NT GEMM: C[m][n] = sum_k A[m][k]*B[n][k].
// Terms: hi*hi (+ hi*lo if B_SPLIT) (+ lo*hi if A_SPLIT).
// QKV_BIAS: bias selected per blockIdx.z from bias0/1/2.
template<int OUT_MODE, bool A_SPLIT, bool B_SPLIT, bool QKV_BIAS>
__global__ void __launch_bounds__(GTHREADS, 2)
f16_gemm(const f16* __restrict__ Ah, const f16* __restrict__ Al,
         const f16* __restrict__ Bh, const f16* __restrict__ Bl,
         const float* __restrict__ bias0, const float* __restrict__ bias1,
         const float* __restrict__ bias2,
         float* __restrict__ Cf, f16* __restrict__ Ch, f16* __restrict__ Cl,
         int M, int N, int K, long sA, long sB, long sC)
{
    extern __shared__ char smem[];
    const uint32_t sbase = smem_u32(smem);
    const int tid  = threadIdx.x;
    const int lane = tid & 31;
    const int wid  = tid >> 5;
    const int wm0  = (wid >> 1) * 64;
    const int wn0  = (wid & 1) * 32;
    const int m0 = blockIdx.y * BM;
    const int n0 = blockIdx.x * BN;

    const float* bias = nullptr;
    if (QKV_BIAS)
        bias = (blockIdx.z == 0) ? bias0 : (blockIdx.z == 1) ? bias1 : bias2;

    const f16* Ahb = Ah + (long)blockIdx.z * sA + (long)m0 * K;
    const f16* Alb = A_SPLIT ? (Al + (long)blockIdx.z * sA + (long)m0 * K) : nullptr;
    const f16* Bhb = Bh + (long)blockIdx.z * sB + (long)n0 * K;
    const f16* Blb = B_SPLIT ? (Bl + (long)blockIdx.z * sB + (long)n0 * K) : nullptr;

    const uint32_t partA = (uint32_t)((wm0 + (lane & 15)) * ROWB
                                      + ((lane >> 4) << 4));
    const uint32_t partB = (uint32_t)((wn0 + (lane & 7) + ((lane >> 4) << 3)) * ROWB
                                      + ((lane & 8) ? 16 : 0));

    float acc[4][4][4];
#pragma unroll
    for (int i = 0; i < 4; i++)
#pragma unroll
        for (int j = 0; j < 4; j++)
#pragma unroll
            for (int r = 0; r < 4; r++) acc[i][j][r] = 0.f;

    const int NC = K / BKE;

    issue_tile<128>(Ahb, sbase + ST_AHI, K, 0, tid);
    if (A_SPLIT) issue_tile<128>(Alb, sbase + ST_ALO, K, 0, tid);
    issue_tile<64> (Bhb, sbase + ST_BHI, K, 0, tid);
    if (B_SPLIT) issue_tile<64> (Blb, sbase + ST_BLO, K, 0, tid);
    CP_COMMIT();

    for (int i = 0; i < NC; i++) {
        __syncthreads();
        if (i + 1 < NC) {
            uint32_t sb = sbase + (uint32_t)(((i + 1) & 1) * STAGEB);
            long k0 = (long)(i + 1) * BKE;
            issue_tile<128>(Ahb, sb + ST_AHI, K, k0, tid);
            if (A_SPLIT) issue_tile<128>(Alb, sb + ST_ALO, K, k0, tid);
            issue_tile<64> (Bhb, sb + ST_BHI, K, k0, tid);
            if (B_SPLIT) issue_tile<64> (Blb, sb + ST_BLO, K, k0, tid);
            CP_COMMIT();
            CP_WAIT(1);
        } else {
            CP_WAIT(0);
        }
        __syncthreads();

        const uint32_t st = sbase + (uint32_t)((i & 1) * STAGEB);
#pragma unroll
        for (int ks = 0; ks < 4; ks++) {
            uint32_t ah[4][4], al[4][4], bh[4][2], bl[4][2];
#pragma unroll
            for (int mf = 0; mf < 4; mf++) {
                uint32_t off = (uint32_t)(mf * 16 * ROWB + ks * 32) + partA;
                ldm_x4(ah[mf], st + ST_AHI + off);
                if (A_SPLIT) ldm_x4(al[mf], st + ST_ALO + off);
            }
#pragma unroll
            for (int nf2 = 0; nf2 < 2; nf2++) {
                uint32_t off = (uint32_t)(nf2 * 16 * ROWB + ks * 32) + partB;
                uint32_t t[4];
                ldm_x4(t, st + ST_BHI + off);
                bh[nf2 * 2][0] = t[0]; bh[nf2 * 2][1] = t[1];
                bh[nf2 * 2 + 1][0] = t[2]; bh[nf2 * 2 + 1][1] = t[3];
                if (B_SPLIT) {
                    ldm_x4(t, st + ST_BLO + off);
                    bl[nf2 * 2][0] = t[0]; bl[nf2 * 2][1] = t[1];
                    bl[nf2 * 2 + 1][0] = t[2]; bl[nf2 * 2 + 1][1] = t[3];
                }
            }
#pragma unroll
            for (int nf = 0; nf < 4; nf++)
#pragma unroll
                for (int mf = 0; mf < 4; mf++) {
                    mma_f16(acc[mf][nf], ah[mf], bh[nf]);
                    if (B_SPLIT) mma_f16(acc[mf][nf], ah[mf], bl[nf]);
                    if (A_SPLIT) mma_f16(acc[mf][nf], al[mf], bh[nf]);
                }
        }
    }

    // epilogue
    const int gid = lane >> 2, tig = lane & 3;
#pragma unroll
    for (int mf = 0; mf < 4; mf++) {
        int r0 = m0 + wm0 + mf * 16 + gid;
#pragma unroll
        for (int nf = 0; nf < 4; nf++) {
            int c0 = n0 + wn0 + nf * 8 + tig * 2;
            float bx = 0.f, by = 0.f;
            if (QKV_BIAS) { bx = bias[c0]; by = bias[c0 + 1]; }
            float x0 = acc[mf][nf][0] + bx, y0 = acc[mf][nf][1] + by;
            float x1 = acc[mf][nf][2] + bx, y1 = acc[mf][nf][3] + by;
            long o0 = (long)(r0) * N + c0 + (long)blockIdx.z * sC;
            long o1 = (long)(r0 + 8) * N + c0 + (long)blockIdx.z * sC;
            if (OUT_MODE == OUT_SPLIT) {
                uint32_t h, l;
                split2(x0, y0, h, l);
                *(uint32_t*)(Ch + o0) = h; *(uint32_t*)(Cl + o0) = l;
                split2(x1, y1, h, l);
                *(uint32_t*)(Ch + o1) = h; *(uint32_t*)(Cl + o1) = l;
            } else {
                float* Cb = Cf + (long)blockIdx.z * sC;
                *(float2*)(Cb + (long)r0 * N + c0) = make_float2(x0, y0);
                *(float2*)(Cb + (long)(r0 + 8) * N + c0) = make_float2(x1, y1);
            }
        }
    }
}

// ---------------- split a ---------------------------------------------------
__global__ void __launch_bounds__(256)
split_kernel(const float* __restrict__ src, f16* __restrict__ h,
             f16* __restrict__ l)
{
    long idx = (long)blockIdx.x * 256 + threadIdx.x;
    float2 v = ((const float2*)src)[idx];
    uint32_t hw, lw;
    split2(v.x, v.y, hw, lw);
    ((uint32_t*)h)[idx] = hw;
    ((uint32_t*)l)[idx] = lw;
}

// ---------------- weight transpose + split (z = which W) --------------------
__global__ void __launch_bounds__(256)
wsplit_kernel(const float* __restrict__ w0, const float* __restrict__ w1,
              const float* __restrict__ w2, f16* __restrict__ h,
              f16* __restrict__ l)
{
    __shared__ float t[32][33];
    const float* w = (blockIdx.z == 0) ? w0 : (blockIdx.z == 1) ? w1 : w2;
    h += (long)blockIdx.z * DIM * DIM;
    l += (long)blockIdx.z * DIM * DIM;
    int x = blockIdx.x * 32 + threadIdx.x;
    int y = blockIdx.y * 32 + threadIdx.y;
#pragma unroll
    for (int j = 0; j < 32; j += 8)
        t[threadIdx.y + j][threadIdx.x] = w[(long)(y + j) * DIM + x];
    __syncthreads();
    x = blockIdx.y * 32 + threadIdx.x;
    y = blockIdx.x * 32 + threadIdx.y;
#pragma unroll
    for (int j = 0; j < 32; j += 8) {
        float v = t[threadIdx.x][threadIdx.y + j];
        f16 hv = __float2half_rn(v);
        h[(long)(y + j) * DIM + x] = hv;
        l[(long)(y + j) * DIM + x] =
            __float2half_rn(v - __half2float(hv));
    }
}

// ---------------- f16 transpose ---------------------------------------------
__global__ void __launch_bounds__(256)
transpose_f16(const uint16_t* __restrict__ src, uint16_t* __restrict__ dst,
              int R, int C, long sS, long sD)
{
    __shared__ uint16_t t[32][33];
    src += (long)blockIdx.z * sS;
    dst += (long)blockIdx.z * sD;
    int x = blockIdx.x * 32 + threadIdx.x;
    int y = blockIdx.y * 32 + threadIdx.y;
#pragma unroll
    for (int j = 0; j < 32; j += 8)
        t[threadIdx.y + j][threadIdx.x] = src[(long)(y + j) * C + x];
    __syncthreads();
    x = blockIdx.y * 32 + threadIdx.x;
    y = blockIdx.x * 32 + threadIdx.y;
#pragma unroll
    for (int j = 0; j < 32; j += 8)
        dst[(long)(y + j) * R + x] = t[threadIdx.x][threadIdx.y + j];
}

// ---------------- softmax -> single fp16 P ----------------------------------
__global__ void __launch_bounds__(256)
softmax_f16(const float* __restrict__ S, f16* __restrict__ Ph)
{
    const float2* row = (const float2*)(S + (long)blockIdx.x * SEQ);
    uint32_t* oh = (uint32_t*)(Ph + (long)blockIdx.x * SEQ);
    __shared__ float red[256];
    const int tid = threadIdx.x;

    float2 e[4];
#pragma unroll
    for (int j = 0; j < 4; j++) e[j] = row[tid + j * 256];

    float m = -INFINITY;
#pragma unroll
    for (int j = 0; j < 4; j++) m = fmaxf(m, fmaxf(e[j].x, e[j].y));
    red[tid] = m;
    __syncthreads();
    for (int s = 128; s > 0; s >>= 1) {
        if (tid < s) red[tid] = fmaxf(red[tid], red[tid + s]);
        __syncthreads();
    }
    m = red[0];
    __syncthreads();

    float sum = 0.f;
#pragma unroll
    for (int j = 0; j < 4; j++) {
        e[j].x = __expf(e[j].x - m);
        e[j].y = __expf(e[j].y - m);
        sum += e[j].x + e[j].y;
    }
    red[tid] = sum;
    __syncthreads();
    for (int s = 128; s > 0; s >>= 1) {
        if (tid < s) red[tid] += red[tid + s];
        __syncthreads();
    }
    float inv = 1.f / red[0];

#pragma unroll
    for (int j = 0; j < 4; j++)
        oh[tid + j * 256] = hpack(__float2half_rn(e[j].x * inv),
                                  __float2half_rn(e[j].y * inv));
}

// ---------------------------------------------------------------------------
extern "C" void kernel_launch(void* const* d_in, const int* in_sizes, int n_in,
                              void* d_out, int out_size)
{
    const float* a   = (const float*)d_in[0];
    const float* w_q = (const float*)d_in[1];
    const float* b_q = (const float*)d_in[2];
    const float* w_k = (const float*)d_in[3];
    const float* b_k = (const float*)d_in[4];
    const float* w_v = (const float*)d_in[5];
    const float* b_v = (const float*)d_in[6];
    float* out = (float*)d_out;

    f16 *ah, *al, *wth, *wtl, *qkvh, *qkvl, *vth, *ph;
    float* s;
    cudaGetSymbolAddress((void**)&ah,   g_ah);   cudaGetSymbolAddress((void**)&al,   g_al);
    cudaGetSymbolAddress((void**)&wth,  g_wth);  cudaGetSymbolAddress((void**)&wtl,  g_wtl);
    cudaGetSymbolAddress((void**)&qkvh, g_qkvh); cudaGetSymbolAddress((void**)&qkvl, g_qkvl);
    cudaGetSymbolAddress((void**)&vth,  g_vth);
    cudaGetSymbolAddress((void**)&ph,   g_ph);
    cudaGetSymbolAddress((void**)&s,    g_s);

    f16 *qh = qkvh,        *ql = qkvl;
    f16 *kh = qkvh + PSL,  *kl = qkvl + PSL;
    f16 *vh = qkvh + 2*PSL;

    cudaFuncSetAttribute(f16_gemm<OUT_SPLIT, true, true, true>,
                         cudaFuncAttributeMaxDynamicSharedMemorySize, SMEM_SZ);
    cudaFuncSetAttribute(f16_gemm<OUT_F32, true, true, false>,
                         cudaFuncAttributeMaxDynamicSharedMemorySize, SMEM_SZ);
    cudaFuncSetAttribute(f16_gemm<OUT_F32, false, false, false>,
                         cudaFuncAttributeMaxDynamicSharedMemorySize, SMEM_SZ);

    // 0) operand prep
    split_kernel<<<(long)M1 * DIM / 512, 256>>>(a, ah, al);
    {
        dim3 grid(DIM / 32, DIM / 32, 3);
        dim3 blk(32, 8, 1);
        wsplit_kernel<<<grid, blk>>>(w_q, w_k, w_v, wth, wtl);
    }

    // 1) ALL projections in ONE launch (z=0:Q, 1:K, 2:V)
    {
        dim3 grid(DIM / BN, M1 / BM, 3);
        f16_gemm<OUT_SPLIT, true, true, true><<<grid, GTHREADS, SMEM_SZ>>>(
            ah, al, wth, wtl, b_q, b_k, b_v,
            nullptr, qkvh, qkvl, M1, DIM, DIM,
            0, (long)DIM * DIM, PSL);
    }

    // 2) vt = transpose(vh)
    {
        dim3 grid(DIM / 32, SEQ / 32, BATCH);
        dim3 blk(32, 8, 1);
        transpose_f16<<<grid, blk>>>((const uint16_t*)vh, (uint16_t*)vth,
                                     SEQ, DIM, (long)SEQ * DIM, (long)DIM * SEQ);
    }

    // 3) scores = q @ k^T (fp32 out, 3-term)
    {
        dim3 grid(SEQ / BN, SEQ / BM, BATCH);
        f16_gemm<OUT_F32, true, true, false><<<grid, GTHREADS, SMEM_SZ>>>(
            qh, ql, kh, kl, nullptr, nullptr, nullptr,
            s, nullptr, nullptr,
            SEQ, SEQ, DIM, (long)SEQ * DIM, (long)SEQ * DIM, (long)SEQ * SEQ);
    }

    // 4) softmax -> single fp16 P
    softmax_f16<<<BATCH * SEQ, 256>>>(s, ph);

    // 5) out = P @ vt^T (fp32 out, 1-term)
    {
        dim3 grid(DIM / BN, SEQ / BM, BATCH);
        f16_gemm<OUT_F32, false, false, false><<<grid, GTHREADS, SMEM_SZ>>>(
            ph, nullptr, vth, nullptr, nullptr, nullptr, nullptr,
            out, nullptr, nullptr,
            SEQ, DIM, SEQ, (long)SEQ * SEQ, (long)DIM * SEQ, (long)SEQ * DIM);
    }
}

// round 14
// speedup vs baseline: 1.3090x; 1.0146x over previous
#include <cuda_runtime.h>
#include <cuda_fp16.h>
#include <cstdint>
#include <math.h>

// ---------------------------------------------------------------------------
// Self-attention B=4, S=2048, D=1024 — Round 13.
// fp16 split GEMMs (mma.sync.m16n8k16). NEW vs R12: 3 CTAs/SM.
//   BKE 64->32 (80B rows), stage 30KB, 2-stage cp.async -> 60KB smem/CTA,
//   __launch_bounds__(128,3). Warp tile 64x32 (2x2 warps) unchanged.
// Merged QKV projection launch (z=0..2), V lo-store skipped (unused).
// Precision (calibrated): Q,K,scores 3-term; P@V 1-term. rel_err ~2.66e-4.
// ---------------------------------------------------------------------------

#define BATCH 4
#define SEQ   2048
#define DIM   1024

typedef __half f16;

#define M1 (BATCH * SEQ)            // 8192
#define PSL ((long)M1 * DIM)

// ---------------- scratch ---------------------------------------------------
__device__ f16   g_ah[PSL], g_al[PSL];
__device__ f16   g_wth[3 * DIM * DIM], g_wtl[3 * DIM * DIM];
__device__ f16   g_qkvh[3 * PSL], g_qkvl[3 * PSL];
__device__ f16   g_vth[BATCH * DIM * SEQ];
__device__ float g_s [BATCH * SEQ * SEQ];
__device__ f16   g_ph[BATCH * SEQ * SEQ];

// ---------------- helpers ---------------------------------------------------
__device__ __forceinline__ uint32_t smem_u32(const void* p) {
    uint32_t a;
    asm("{ .reg .u64 t; cvta.to.shared.u64 t, %1; cvt.u32.u64 %0, t; }"
        : "=r"(a) : "l"(p));
    return a;
}
__device__ __forceinline__ void cp16(uint32_t dst, const void* src) {
    asm volatile("cp.async.cg.shared.global [%0], [%1], 16;"
                 :: "r"(dst), "l"(src));
}
#define CP_COMMIT() asm volatile("cp.async.commit_group;" ::: "memory")
#define CP_WAIT(n)  asm volatile("cp.async.wait_group %0;" :: "n"(n) : "memory")

__device__ __forceinline__ void ldm_x4(uint32_t* r, uint32_t addr) {
    asm volatile("ldmatrix.sync.aligned.m8n8.x4.shared.b16 {%0,%1,%2,%3}, [%4];"
                 : "=r"(r[0]), "=r"(r[1]), "=r"(r[2]), "=r"(r[3]) : "r"(addr));
}
__device__ __forceinline__ void mma_f16(float* c, const uint32_t* a,
                                        const uint32_t* b) {
    asm volatile(
        "mma.sync.aligned.m16n8k16.row.col.f32.f16.f16.f32 "
        "{%0,%1,%2,%3}, {%4,%5,%6,%7}, {%8,%9}, {%0,%1,%2,%3};"
        : "+f"(c[0]), "+f"(c[1]), "+f"(c[2]), "+f"(c[3])
        : "r"(a[0]), "r"(a[1]), "r"(a[2]), "r"(a[3]), "r"(b[0]), "r"(b[1]));
}
__device__ __forceinline__ uint32_t hpack(f16 a, f16 b) {
    union { __half2 v; uint32_t u; } t;
    t.v = __halves2half2(a, b);
    return t.u;
}
__device__ __forceinline__ void split2(float x, float y, uint32_t& hi,
                                       uint32_t& lo) {
    f16 hx = __float2half_rn(x), hy = __float2half_rn(y);
    hi = hpack(hx, hy);
    lo = hpack(__float2half_rn(x - __half2float(hx)),
               __float2half_rn(y - __half2float(hy)));
}

// ---------------- GEMM config ----------------------------------------------
#define BM 128
#define BN 64
#define BKE 32                 // fp16 elems per stage (2 x k16)
#define GTHREADS 128           // 4 warps: 2(M) x 2(N), warp tile 64x32

#define ROWB   80              // 64B data + 16B pad
#define AT_B   (128 * ROWB)    // 10240
#define BT_B   (64 * ROWB)     // 5120
#define ST_AHI 0
#define ST_ALO (AT_B)
#define ST_BHI (2 * AT_B)
#define ST_BLO (2 * AT_B + BT_B)
#define STAGEB (2 * AT_B + 2 * BT_B)        // 30720
#define SMEM_SZ (2 * STAGEB)                // 61440 -> 3 CTAs/SM

#define OUT_F32   0
#define OUT_SPLIT 1

// tile: R rows x 32 fp16 (64B) per row -> R*4 cp16 ops
template<int R>
__device__ __forceinline__ void issue_tile(const f16* src, uint32_t dst,
                                           int K, long k0, int tid) {
#pragma unroll
    for (int it = 0; it < R * 4 / GTHREADS; it++) {
        int c = tid + it * GTHREADS;
        int row = c >> 2, col = c & 3;
        cp16(dst + row * ROWB + col * 16, src + (long)row * K + k0 + col * 8);
    }
}

// NT GEMM: C[m][n] = sum_k A[m][k]*B[n][k].
// Terms: hi*hi (+ hi*lo if B_SPLIT) (+ lo*hi if A_SPLIT).
template<int OUT_MODE, bool A_SPLIT, bool B_SPLIT, bool QKV_BIAS>
__global__ void __launch_bounds__(GTHREADS, 3)
f16_gemm(const f16* __restrict__ Ah, const f16* __restrict__ Al,
         const f16* __restrict__ Bh, const f16* __restrict__ Bl,
         const float* __restrict__ bias0, const float* __restrict__ bias1,
         const float* __restrict__ bias2,
         float* __restrict__ Cf, f16* __restrict__ Ch, f16* __restrict__ Cl,
         int M, int N, int K, long sA, long sB, long sC)
{
    extern __shared__ char smem[];
    const uint32_t sbase = smem_u32(smem);
    const int tid  = threadIdx.x;
    const int lane = tid & 31;
    const int wid  = tid >> 5;
    const int wm0  = (wid >> 1) * 64;
    const int wn0  = (wid & 1) * 32;
    const int m0 = blockIdx.y * BM;
    const int n0 = blockIdx.x * BN;

    const float* bias = nullptr;
    if (QKV_BIAS)
        bias = (blockIdx.z == 0) ? bias0 : (blockIdx.z == 1) ? bias1 : bias2;

    const f16* Ahb = Ah + (long)blockIdx.z * sA + (long)m0 * K;
    const f16* Alb = A_SPLIT ? (Al + (long)blockIdx.z * sA + (long)m0 * K) : nullptr;
    const f16* Bhb = Bh + (long)blockIdx.z * sB + (long)n0 * K;
    const f16* Blb = B_SPLIT ? (Bl + (long)blockIdx.z * sB + (long)n0 * K) : nullptr;

    const uint32_t partA = (uint32_t)((wm0 + (lane & 15)) * ROWB
                                      + ((lane >> 4) << 4));
    const uint32_t partB = (uint32_t)((wn0 + (lane & 7) + ((lane >> 4) << 3)) * ROWB
                                      + ((lane & 8) ? 16 : 0));

    float acc[4][4][4];
#pragma unroll
    for (int i = 0; i < 4; i++)
#pragma unroll
        for (int j = 0; j < 4; j++)
#pragma unroll
            for (int r = 0; r < 4; r++) acc[i][j][r] = 0.f;

    const int NC = K / BKE;

    issue_tile<128>(Ahb, sbase + ST_AHI, K, 0, tid);
    if (A_SPLIT) issue_tile<128>(Alb, sbase + ST_ALO, K, 0, tid);
    issue_tile<64> (Bhb, sbase + ST_BHI, K, 0, tid);
    if (B_SPLIT) issue_tile<64> (Blb, sbase + ST_BLO, K, 0, tid);
    CP_COMMIT();

    for (int i = 0; i < NC; i++) {
        __syncthreads();
        if (i + 1 < NC) {
            uint32_t sb = sbase + (uint32_t)(((i + 1) & 1) * STAGEB);
            long k0 = (long)(i + 1) * BKE;
            issue_tile<128>(Ahb, sb + ST_AHI, K, k0, tid);
            if (A_SPLIT) issue_tile<128>(Alb, sb + ST_ALO, K, k0, tid);
            issue_tile<64> (Bhb, sb + ST_BHI, K, k0, tid);
            if (B_SPLIT) issue_tile<64> (Blb, sb + ST_BLO, K, k0, tid);
            CP_COMMIT();
            CP_WAIT(1);
        } else {
            CP_WAIT(0);
        }
        __syncthreads();

        const uint32_t st = sbase + (uint32_t)((i & 1) * STAGEB);
#pragma unroll
        for (int ks = 0; ks < 2; ks++) {
            uint32_t ah[4][4], al[4][4], bh[4][2], bl[4][2];
#pragma unroll
            for (int mf = 0; mf < 4; mf++) {
                uint32_t off = (uint32_t)(mf * 16 * ROWB + ks * 32) + partA;
                ldm_x4(ah[mf], st + ST_AHI + off);
                if (A_SPLIT) ldm_x4(al[mf], st + ST_ALO + off);
            }
#pragma unroll
            for (int nf2 = 0; nf2 < 2; nf2++) {
                uint32_t off = (uint32_t)(nf2 * 16 * ROWB + ks * 32) + partB;
                uint32_t t[4];
                ldm_x4(t, st + ST_BHI + off);
                bh[nf2 * 2][0] = t[0]; bh[nf2 * 2][1] = t[1];
                bh[nf2 * 2 + 1][0] = t[2]; bh[nf2 * 2 + 1][1] = t[3];
                if (B_SPLIT) {
                    ldm_x4(t, st + ST_BLO + off);
                    bl[nf2 * 2][0] = t[0]; bl[nf2 * 2][1] = t[1];
                    bl[nf2 * 2 + 1][0] = t[2]; bl[nf2 * 2 + 1][1] = t[3];
                }
            }
#pragma unroll
            for (int nf = 0; nf < 4; nf++)
#pragma unroll
                for (int mf = 0; mf < 4; mf++) {
                    mma_f16(acc[mf][nf], ah[mf], bh[nf]);
                    if (B_SPLIT) mma_f16(acc[mf][nf], ah[mf], bl[nf]);
                    if (A_SPLIT) mma_f16(acc[mf][nf], al[mf], bh[nf]);
                }
        }
    }

    // epilogue
    const int gid = lane >> 2, tig = lane & 3;
#pragma unroll
    for (int mf = 0; mf < 4; mf++) {
        int r0 = m0 + wm0 + mf * 16 + gid;
#pragma unroll
        for (int nf = 0; nf < 4; nf++) {
            int c0 = n0 + wn0 + nf * 8 + tig * 2;
            float bx = 0.f, by = 0.f;
            if (QKV_BIAS) { bx = bias[c0]; by = bias[c0 + 1]; }
            float x0 = acc[mf][nf][0] + bx, y0 = acc[mf][nf][1] + by;
            float x1 = acc[mf][nf][2] + bx, y1 = acc[mf][nf][3] + by;
            long o0 = (long)(r0) * N + c0 + (long)blockIdx.z * sC;
            long o1 = (long)(r0 + 8) * N + c0 + (long)blockIdx.z * sC;
            if (OUT_MODE == OUT_SPLIT) {
                uint32_t h, l;
                split2(x0, y0, h, l);
                *(uint32_t*)(Ch + o0) = h;
                if (!QKV_BIAS || blockIdx.z < 2) *(uint32_t*)(Cl + o0) = l;
                split2(x1, y1, h, l);
                *(uint32_t*)(Ch + o1) = h;
                if (!QKV_BIAS || blockIdx.z < 2) *(uint32_t*)(Cl + o1) = l;
            } else {
                float* Cb = Cf + (long)blockIdx.z * sC;
                *(float2*)(Cb + (long)r0 * N + c0) = make_float2(x0, y0);
                *(float2*)(Cb + (long)(r0 + 8) * N + c0) = make_float2(x1, y1);
            }
        }
    }
}

// ---------------- split a ---------------------------------------------------
__global__ void __launch_bounds__(256)
split_kernel(const float* __restrict__ src, f16* __restrict__ h,
             f16* __restrict__ l)
{
    long idx = (long)blockIdx.x * 256 + threadIdx.x;
    float2 v = ((const float2*)src)[idx];
    uint32_t hw, lw;
    split2(v.x, v.y, hw, lw);
    ((uint32_t*)h)[idx] = hw;
    ((uint32_t*)l)[idx] = lw;
}

// ---------------- weight transpose + split ----------------------------------
__global__ void __launch_bounds__(256)
wsplit_kernel(const float* __restrict__ w0, const float* __restrict__ w1,
              const float* __restrict__ w2, f16* __restrict__ h,
              f16* __restrict__ l)
{
    __shared__ float t[32][33];
    const float* w = (blockIdx.z == 0) ? w0 : (blockIdx.z == 1) ? w1 : w2;
    h += (long)blockIdx.z * DIM * DIM;
    l += (long)blockIdx.z * DIM * DIM;
    int x = blockIdx.x * 32 + threadIdx.x;
    int y = blockIdx.y * 32 + threadIdx.y;
#pragma unroll
    for (int j = 0; j < 32; j += 8)
        t[threadIdx.y + j][threadIdx.x] = w[(long)(y + j) * DIM + x];
    __syncthreads();
    x = blockIdx.y * 32 + threadIdx.x;
    y = blockIdx.x * 32 + threadIdx.y;
#pragma unroll
    for (int j = 0; j < 32; j += 8) {
        float v = t[threadIdx.x][threadIdx.y + j];
        f16 hv = __float2half_rn(v);
        h[(long)(y + j) * DIM + x] = hv;
        l[(long)(y + j) * DIM + x] =
            __float2half_rn(v - __half2float(hv));
    }
}

// ---------------- f16 transpose ---------------------------------------------
__global__ void __launch_bounds__(256)
transpose_f16(const uint16_t* __restrict__ src, uint16_t* __restrict__ dst,
              int R, int C, long sS, long sD)
{
    __shared__ uint16_t t[32][33];
    src += (long)blockIdx.z * sS;
    dst += (long)blockIdx.z * sD;
    int x = blockIdx.x * 32 + threadIdx.x;
    int y = blockIdx.y * 32 + threadIdx.y;
#pragma unroll
    for (int j = 0; j < 32; j += 8)
        t[threadIdx.y + j][threadIdx.x] = src[(long)(y + j) * C + x];
    __syncthreads();
    x = blockIdx.y * 32 + threadIdx.x;
    y = blockIdx.x * 32 + threadIdx.y;
#pragma unroll
    for (int j = 0; j < 32; j += 8)
        dst[(long)(y + j) * R + x] = t[threadIdx.x][threadIdx.y + j];
}

// ---------------- softmax -> single fp16 P ----------------------------------
__global__ void __launch_bounds__(256)
softmax_f16(const float* __restrict__ S, f16* __restrict__ Ph)
{
    const float2* row = (const float2*)(S + (long)blockIdx.x * SEQ);
    uint32_t* oh = (uint32_t*)(Ph + (long)blockIdx.x * SEQ);
    __shared__ float red[256];
    const int tid = threadIdx.x;

    float2 e[4];
#pragma unroll
    for (int j = 0; j < 4; j++) e[j] = row[tid + j * 256];

    float m = -INFINITY;
#pragma unroll
    for (int j = 0; j < 4; j++) m = fmaxf(m, fmaxf(e[j].x, e[j].y));
    red[tid] = m;
    __syncthreads();
    for (int s = 128; s > 0; s >>= 1) {
        if (tid < s) red[tid] = fmaxf(red[tid], red[tid + s]);
        __syncthreads();
    }
    m = red[0];
    __syncthreads();

    float sum = 0.f;
#pragma unroll
    for (int j = 0; j < 4; j++) {
        e[j].x = __expf(e[j].x - m);
        e[j].y = __expf(e[j].y - m);
        sum += e[j].x + e[j].y;
    }
    red[tid] = sum;
    __syncthreads();
    for (int s = 128; s > 0; s >>= 1) {
        if (tid < s) red[tid] += red[tid + s];
        __syncthreads();
    }
    float inv = 1.f / red[0];

#pragma unroll
    for (int j = 0; j < 4; j++)
        oh[tid + j * 256] = hpack(__float2half_rn(e[j].x * inv),
                                  __float2half_rn(e[j].y * inv));
}

// ---------------------------------------------------------------------------
extern "C" void kernel_launch(void* const* d_in, const int* in_sizes, int n_in,
                              void* d_out, int out_size)
{
    const float* a   = (const float*)d_in[0];
    const float* w_q = (const float*)d_in[1];
    const float* b_q = (const float*)d_in[2];
    const float* w_k = (const float*)d_in[3];
    const float* b_k = (const float*)d_in[4];
    const float* w_v = (const float*)d_in[5];
    const float* b_v = (const float*)d_in[6];
    float* out = (float*)d_out;

    f16 *ah, *al, *wth, *wtl, *qkvh, *qkvl, *vth, *ph;
    float* s;
    cudaGetSymbolAddress((void**)&ah,   g_ah);   cudaGetSymbolAddress((void**)&al,   g_al);
    cudaGetSymbolAddress((void**)&wth,  g_wth);  cudaGetSymbolAddress((void**)&wtl,  g_wtl);
    cudaGetSymbolAddress((void**)&qkvh, g_qkvh); cudaGetSymbolAddress((void**)&qkvl, g_qkvl);
    cudaGetSymbolAddress((void**)&vth,  g_vth);
    cudaGetSymbolAddress((void**)&ph,   g_ph);
    cudaGetSymbolAddress((void**)&s,    g_s);

    f16 *qh = qkvh,        *ql = qkvl;
    f16 *kh = qkvh + PSL,  *kl = qkvl + PSL;
    f16 *vh = qkvh + 2*PSL;

    cudaFuncSetAttribute(f16_gemm<OUT_SPLIT, true, true, true>,
                         cudaFuncAttributeMaxDynamicSharedMemorySize, SMEM_SZ);
    cudaFuncSetAttribute(f16_gemm<OUT_F32, true, true, false>,
                         cudaFuncAttributeMaxDynamicSharedMemorySize, SMEM_SZ);
    cudaFuncSetAttribute(f16_gemm<OUT_F32, false, false, false>,
                         cudaFuncAttributeMaxDynamicSharedMemorySize, SMEM_SZ);

    // 0) operand prep
    split_kernel<<<(long)M1 * DIM / 512, 256>>>(a, ah, al);
    {
        dim3 grid(DIM / 32, DIM / 32, 3);
        dim3 blk(32, 8, 1);
        wsplit_kernel<<<grid, blk>>>(w_q, w_k, w_v, wth, wtl);
    }

    // 1) ALL projections in ONE launch (z=0:Q, 1:K, 2:V)
    {
        dim3 grid(DIM / BN, M1 / BM, 3);
        f16_gemm<OUT_SPLIT, true, true, true><<<grid, GTHREADS, SMEM_SZ>>>(
            ah, al, wth, wtl, b_q, b_k, b_v,
            nullptr, qkvh, qkvl, M1, DIM, DIM,
            0, (long)DIM * DIM, PSL);
    }

    // 2) vt = transpose(vh)
    {
        dim3 grid(DIM / 32, SEQ / 32, BATCH);
        dim3 blk(32, 8, 1);
        transpose_f16<<<grid, blk>>>((const uint16_t*)vh, (uint16_t*)vth,
                                     SEQ, DIM, (long)SEQ * DIM, (long)DIM * SEQ);
    }

    // 3) scores = q @ k^T (fp32 out, 3-term)
    {
        dim3 grid(SEQ / BN, SEQ / BM, BATCH);
        f16_gemm<OUT_F32, true, true, false><<<grid, GTHREADS, SMEM_SZ>>>(
            qh, ql, kh, kl, nullptr, nullptr, nullptr,
            s, nullptr, nullptr,
            SEQ, SEQ, DIM, (long)SEQ * DIM, (long)SEQ * DIM, (long)SEQ * SEQ);
    }

    // 4) softmax -> single fp16 P
    softmax_f16<<<BATCH * SEQ, 256>>>(s, ph);

    // 5) out = P @ vt^T (fp32 out, 1-term)
    {
        dim3 grid(DIM / BN, SEQ / BM, BATCH);
        f16_gemm<OUT_F32, false, false, false><<<grid, GTHREADS, SMEM_SZ>>>(
            ph, nullptr, vth, nullptr, nullptr, nullptr, nullptr,
            out, nullptr, nullptr,
            SEQ, DIM, SEQ, (long)SEQ * SEQ, (long)DIM * SEQ, (long)SEQ * DIM);
    }
}

// round 15
// speedup vs baseline: 1.3285x; 1.0149x over previous
#include <cuda_runtime.h>
#include <cuda_fp16.h>
#include <cstdint>
#include <math.h>

// ---------------------------------------------------------------------------
// Self-attention B=4, S=2048, D=1024 — Round 14.
// vs R13: (1) GEMM smem stage offsets are template-constexpr -> 1-term P@V
// uses half the smem (30KB/CTA) + MINB=4 reg cap -> 4 CTAs/SM, smaller tail.
// (2) softmax rewritten: float4 IO, warp-shuffle reductions, uint2 P writes.
// Precision (calibrated): Q,K,scores 3-term; P@V 1-term. rel_err ~2.66e-4.
// ---------------------------------------------------------------------------

#define BATCH 4
#define SEQ   2048
#define DIM   1024

typedef __half f16;

#define M1 (BATCH * SEQ)            // 8192
#define PSL ((long)M1 * DIM)

// ---------------- scratch ---------------------------------------------------
__device__ f16   g_ah[PSL], g_al[PSL];
__device__ f16   g_wth[3 * DIM * DIM], g_wtl[3 * DIM * DIM];
__device__ f16   g_qkvh[3 * PSL], g_qkvl[3 * PSL];
__device__ f16   g_vth[BATCH * DIM * SEQ];
__device__ float g_s [BATCH * SEQ * SEQ];
__device__ f16   g_ph[BATCH * SEQ * SEQ];

// ---------------- helpers ---------------------------------------------------
__device__ __forceinline__ uint32_t smem_u32(const void* p) {
    uint32_t a;
    asm("{ .reg .u64 t; cvta.to.shared.u64 t, %1; cvt.u32.u64 %0, t; }"
        : "=r"(a) : "l"(p));
    return a;
}
__device__ __forceinline__ void cp16(uint32_t dst, const void* src) {
    asm volatile("cp.async.cg.shared.global [%0], [%1], 16;"
                 :: "r"(dst), "l"(src));
}
#define CP_COMMIT() asm volatile("cp.async.commit_group;" ::: "memory")
#define CP_WAIT(n)  asm volatile("cp.async.wait_group %0;" :: "n"(n) : "memory")

__device__ __forceinline__ void ldm_x4(uint32_t* r, uint32_t addr) {
    asm volatile("ldmatrix.sync.aligned.m8n8.x4.shared.b16 {%0,%1,%2,%3}, [%4];"
                 : "=r"(r[0]), "=r"(r[1]), "=r"(r[2]), "=r"(r[3]) : "r"(addr));
}
__device__ __forceinline__ void mma_f16(float* c, const uint32_t* a,
                                        const uint32_t* b) {
    asm volatile(
        "mma.sync.aligned.m16n8k16.row.col.f32.f16.f16.f32 "
        "{%0,%1,%2,%3}, {%4,%5,%6,%7}, {%8,%9}, {%0,%1,%2,%3};"
        : "+f"(c[0]), "+f"(c[1]), "+f"(c[2]), "+f"(c[3])
        : "r"(a[0]), "r"(a[1]), "r"(a[2]), "r"(a[3]), "r"(b[0]), "r"(b[1]));
}
__device__ __forceinline__ uint32_t hpack(f16 a, f16 b) {
    union { __half2 v; uint32_t u; } t;
    t.v = __halves2half2(a, b);
    return t.u;
}
__device__ __forceinline__ void split2(float x, float y, uint32_t& hi,
                                       uint32_t& lo) {
    f16 hx = __float2half_rn(x), hy = __float2half_rn(y);
    hi = hpack(hx, hy);
    lo = hpack(__float2half_rn(x - __half2float(hx)),
               __float2half_rn(y - __half2float(hy)));
}

// ---------------- GEMM config ----------------------------------------------
#define BM 128
#define BN 64
#define BKE 32                 // fp16 elems per stage (2 x k16)
#define GTHREADS 128           // 4 warps: 2(M) x 2(N), warp tile 64x32

#define ROWB   80              // 64B data + 16B pad
#define AT_B   (128 * ROWB)    // 10240
#define BT_B   (64 * ROWB)     // 5120

#define OUT_F32   0
#define OUT_SPLIT 1

// host-side smem sizes (mirror kernel constexpr)
#define SMEM_FULL (2 * (2 * AT_B + 2 * BT_B))   // 61440: 3 CTAs/SM
#define SMEM_PV   (2 * (AT_B + BT_B))           // 30720: 4 CTAs/SM

template<int R>
__device__ __forceinline__ void issue_tile(const f16* src, uint32_t dst,
                                           int K, long k0, int tid) {
#pragma unroll
    for (int it = 0; it < R * 4 / GTHREADS; it++) {
        int c = tid + it * GTHREADS;
        int row = c >> 2, col = c & 3;
        cp16(dst + row * ROWB + col * 16, src + (long)row * K + k0 + col * 8);
    }
}

// NT GEMM: C[m][n] = sum_k A[m][k]*B[n][k].
// Terms: hi*hi (+ hi*lo if B_SPLIT) (+ lo*hi if A_SPLIT).
template<int OUT_MODE, bool A_SPLIT, bool B_SPLIT, bool QKV_BIAS, int MINB>
__global__ void __launch_bounds__(GTHREADS, MINB)
f16_gemm(const f16* __restrict__ Ah, const f16* __restrict__ Al,
         const f16* __restrict__ Bh, const f16* __restrict__ Bl,
         const float* __restrict__ bias0, const float* __restrict__ bias1,
         const float* __restrict__ bias2,
         float* __restrict__ Cf, f16* __restrict__ Ch, f16* __restrict__ Cl,
         int M, int N, int K, long sA, long sB, long sC)
{
    // stage layout depends on which tiles exist
    constexpr uint32_t O_ALO = AT_B;
    constexpr uint32_t O_BHI = AT_B * (A_SPLIT ? 2 : 1);
    constexpr uint32_t O_BLO = O_BHI + BT_B;
    constexpr uint32_t STB   = O_BHI + BT_B * (B_SPLIT ? 2 : 1);

    extern __shared__ char smem[];
    const uint32_t sbase = smem_u32(smem);
    const int tid  = threadIdx.x;
    const int lane = tid & 31;
    const int wid  = tid >> 5;
    const int wm0  = (wid >> 1) * 64;
    const int wn0  = (wid & 1) * 32;
    const int m0 = blockIdx.y * BM;
    const int n0 = blockIdx.x * BN;

    const float* bias = nullptr;
    if (QKV_BIAS)
        bias = (blockIdx.z == 0) ? bias0 : (blockIdx.z == 1) ? bias1 : bias2;

    const f16* Ahb = Ah + (long)blockIdx.z * sA + (long)m0 * K;
    const f16* Alb = A_SPLIT ? (Al + (long)blockIdx.z * sA + (long)m0 * K) : nullptr;
    const f16* Bhb = Bh + (long)blockIdx.z * sB + (long)n0 * K;
    const f16* Blb = B_SPLIT ? (Bl + (long)blockIdx.z * sB + (long)n0 * K) : nullptr;

    const uint32_t partA = (uint32_t)((wm0 + (lane & 15)) * ROWB
                                      + ((lane >> 4) << 4));
    const uint32_t partB = (uint32_t)((wn0 + (lane & 7) + ((lane >> 4) << 3)) * ROWB
                                      + ((lane & 8) ? 16 : 0));

    float acc[4][4][4];
#pragma unroll
    for (int i = 0; i < 4; i++)
#pragma unroll
        for (int j = 0; j < 4; j++)
#pragma unroll
            for (int r = 0; r < 4; r++) acc[i][j][r] = 0.f;

    const int NC = K / BKE;

    issue_tile<128>(Ahb, sbase + 0, K, 0, tid);
    if (A_SPLIT) issue_tile<128>(Alb, sbase + O_ALO, K, 0, tid);
    issue_tile<64> (Bhb, sbase + O_BHI, K, 0, tid);
    if (B_SPLIT) issue_tile<64> (Blb, sbase + O_BLO, K, 0, tid);
    CP_COMMIT();

    for (int i = 0; i < NC; i++) {
        __syncthreads();
        if (i + 1 < NC) {
            uint32_t sb = sbase + (uint32_t)(((i + 1) & 1) * STB);
            long k0 = (long)(i + 1) * BKE;
            issue_tile<128>(Ahb, sb + 0, K, k0, tid);
            if (A_SPLIT) issue_tile<128>(Alb, sb + O_ALO, K, k0, tid);
            issue_tile<64> (Bhb, sb + O_BHI, K, k0, tid);
            if (B_SPLIT) issue_tile<64> (Blb, sb + O_BLO, K, k0, tid);
            CP_COMMIT();
            CP_WAIT(1);
        } else {
            CP_WAIT(0);
        }
        __syncthreads();

        const uint32_t st = sbase + (uint32_t)((i & 1) * STB);
#pragma unroll
        for (int ks = 0; ks < 2; ks++) {
            uint32_t ah[4][4], al[4][4], bh[4][2], bl[4][2];
#pragma unroll
            for (int mf = 0; mf < 4; mf++) {
                uint32_t off = (uint32_t)(mf * 16 * ROWB + ks * 32) + partA;
                ldm_x4(ah[mf], st + 0 + off);
                if (A_SPLIT) ldm_x4(al[mf], st + O_ALO + off);
            }
#pragma unroll
            for (int nf2 = 0; nf2 < 2; nf2++) {
                uint32_t off = (uint32_t)(nf2 * 16 * ROWB + ks * 32) + partB;
                uint32_t t[4];
                ldm_x4(t, st + O_BHI + off);
                bh[nf2 * 2][0] = t[0]; bh[nf2 * 2][1] = t[1];
                bh[nf2 * 2 + 1][0] = t[2]; bh[nf2 * 2 + 1][1] = t[3];
                if (B_SPLIT) {
                    ldm_x4(t, st + O_BLO + off);
                    bl[nf2 * 2][0] = t[0]; bl[nf2 * 2][1] = t[1];
                    bl[nf2 * 2 + 1][0] = t[2]; bl[nf2 * 2 + 1][1] = t[3];
                }
            }
#pragma unroll
            for (int nf = 0; nf < 4; nf++)
#pragma unroll
                for (int mf = 0; mf < 4; mf++) {
                    mma_f16(acc[mf][nf], ah[mf], bh[nf]);
                    if (B_SPLIT) mma_f16(acc[mf][nf], ah[mf], bl[nf]);
                    if (A_SPLIT) mma_f16(acc[mf][nf], al[mf], bh[nf]);
                }
        }
    }

    // epilogue
    const int gid = lane >> 2, tig = lane & 3;
#pragma unroll
    for (int mf = 0; mf < 4; mf++) {
        int r0 = m0 + wm0 + mf * 16 + gid;
#pragma unroll
        for (int nf = 0; nf < 4; nf++) {
            int c0 = n0 + wn0 + nf * 8 + tig * 2;
            float bx = 0.f, by = 0.f;
            if (QKV_BIAS) { bx = bias[c0]; by = bias[c0 + 1]; }
            float x0 = acc[mf][nf][0] + bx, y0 = acc[mf][nf][1] + by;
            float x1 = acc[mf][nf][2] + bx, y1 = acc[mf][nf][3] + by;
            long o0 = (long)(r0) * N + c0 + (long)blockIdx.z * sC;
            long o1 = (long)(r0 + 8) * N + c0 + (long)blockIdx.z * sC;
            if (OUT_MODE == OUT_SPLIT) {
                uint32_t h, l;
                split2(x0, y0, h, l);
                *(uint32_t*)(Ch + o0) = h;
                if (!QKV_BIAS || blockIdx.z < 2) *(uint32_t*)(Cl + o0) = l;
                split2(x1, y1, h, l);
                *(uint32_t*)(Ch + o1) = h;
                if (!QKV_BIAS || blockIdx.z < 2) *(uint32_t*)(Cl + o1) = l;
            } else {
                float* Cb = Cf + (long)blockIdx.z * sC;
                *(float2*)(Cb + (long)r0 * N + c0) = make_float2(x0, y0);
                *(float2*)(Cb + (long)(r0 + 8) * N + c0) = make_float2(x1, y1);
            }
        }
    }
}

// ---------------- split a ---------------------------------------------------
__global__ void __launch_bounds__(256)
split_kernel(const float* __restrict__ src, f16* __restrict__ h,
             f16* __restrict__ l)
{
    long idx = (long)blockIdx.x * 256 + threadIdx.x;
    float2 v = ((const float2*)src)[idx];
    uint32_t hw, lw;
    split2(v.x, v.y, hw, lw);
    ((uint32_t*)h)[idx] = hw;
    ((uint32_t*)l)[idx] = lw;
}

// ---------------- weight transpose + split ----------------------------------
__global__ void __launch_bounds__(256)
wsplit_kernel(const float* __restrict__ w0, const float* __restrict__ w1,
              const float* __restrict__ w2, f16* __restrict__ h,
              f16* __restrict__ l)
{
    __shared__ float t[32][33];
    const float* w = (blockIdx.z == 0) ? w0 : (blockIdx.z == 1) ? w1 : w2;
    h += (long)blockIdx.z * DIM * DIM;
    l += (long)blockIdx.z * DIM * DIM;
    int x = blockIdx.x * 32 + threadIdx.x;
    int y = blockIdx.y * 32 + threadIdx.y;
#pragma unroll
    for (int j = 0; j < 32; j += 8)
        t[threadIdx.y + j][threadIdx.x] = w[(long)(y + j) * DIM + x];
    __syncthreads();
    x = blockIdx.y * 32 + threadIdx.x;
    y = blockIdx.x * 32 + threadIdx.y;
#pragma unroll
    for (int j = 0; j < 32; j += 8) {
        float v = t[threadIdx.x][threadIdx.y + j];
        f16 hv = __float2half_rn(v);
        h[(long)(y + j) * DIM + x] = hv;
        l[(long)(y + j) * DIM + x] =
            __float2half_rn(v - __half2float(hv));
    }
}

// ---------------- f16 transpose ---------------------------------------------
__global__ void __launch_bounds__(256)
transpose_f16(const uint16_t* __restrict__ src, uint16_t* __restrict__ dst,
              int R, int C, long sS, long sD)
{
    __shared__ uint16_t t[32][33];
    src += (long)blockIdx.z * sS;
    dst += (long)blockIdx.z * sD;
    int x = blockIdx.x * 32 + threadIdx.x;
    int y = blockIdx.y * 32 + threadIdx.y;
#pragma unroll
    for (int j = 0; j < 32; j += 8)
        t[threadIdx.y + j][threadIdx.x] = src[(long)(y + j) * C + x];
    __syncthreads();
    x = blockIdx.y * 32 + threadIdx.x;
    y = blockIdx.x * 32 + threadIdx.y;
#pragma unroll
    for (int j = 0; j < 32; j += 8)
        dst[(long)(y + j) * R + x] = t[threadIdx.x][threadIdx.y + j];
}

// ---------------- softmax -> single fp16 P (float4 + shuffle) ---------------
__global__ void __launch_bounds__(256)
softmax_f16(const float* __restrict__ S, f16* __restrict__ Ph)
{
    const float4* row = (const float4*)(S + (long)blockIdx.x * SEQ);
    uint2* oh = (uint2*)(Ph + (long)blockIdx.x * SEQ);
    __shared__ float wmax[8], wsum[8];
    const int tid  = threadIdx.x;
    const int lane = tid & 31;
    const int wrp  = tid >> 5;

    float4 e0 = row[tid], e1 = row[tid + 256];

    // row max
    float m = fmaxf(fmaxf(fmaxf(e0.x, e0.y), fmaxf(e0.z, e0.w)),
                    fmaxf(fmaxf(e1.x, e1.y), fmaxf(e1.z, e1.w)));
#pragma unroll
    for (int o = 16; o > 0; o >>= 1)
        m = fmaxf(m, __shfl_xor_sync(0xFFFFFFFFu, m, o));
    if (lane == 0) wmax[wrp] = m;
    __syncthreads();
    m = wmax[0];
#pragma unroll
    for (int j = 1; j < 8; j++) m = fmaxf(m, wmax[j]);

    // exp + row sum
    e0.x = __expf(e0.x - m); e0.y = __expf(e0.y - m);
    e0.z = __expf(e0.z - m); e0.w = __expf(e0.w - m);
    e1.x = __expf(e1.x - m); e1.y = __expf(e1.y - m);
    e1.z = __expf(e1.z - m); e1.w = __expf(e1.w - m);
    float s = (e0.x + e0.y) + (e0.z + e0.w) + (e1.x + e1.y) + (e1.z + e1.w);
#pragma unroll
    for (int o = 16; o > 0; o >>= 1)
        s += __shfl_xor_sync(0xFFFFFFFFu, s, o);
    if (lane == 0) wsum[wrp] = s;
    __syncthreads();
    s = wsum[0];
#pragma unroll
    for (int j = 1; j < 8; j++) s += wsum[j];
    float inv = 1.f / s;

    uint2 p0, p1;
    p0.x = hpack(__float2half_rn(e0.x * inv), __float2half_rn(e0.y * inv));
    p0.y = hpack(__float2half_rn(e0.z * inv), __float2half_rn(e0.w * inv));
    p1.x = hpack(__float2half_rn(e1.x * inv), __float2half_rn(e1.y * inv));
    p1.y = hpack(__float2half_rn(e1.z * inv), __float2half_rn(e1.w * inv));
    oh[tid] = p0;
    oh[tid + 256] = p1;
}

// ---------------------------------------------------------------------------
extern "C" void kernel_launch(void* const* d_in, const int* in_sizes, int n_in,
                              void* d_out, int out_size)
{
    const float* a   = (const float*)d_in[0];
    const float* w_q = (const float*)d_in[1];
    const float* b_q = (const float*)d_in[2];
    const float* w_k = (const float*)d_in[3];
    const float* b_k = (const float*)d_in[4];
    const float* w_v = (const float*)d_in[5];
    const float* b_v = (const float*)d_in[6];
    float* out = (float*)d_out;

    f16 *ah, *al, *wth, *wtl, *qkvh, *qkvl, *vth, *ph;
    float* s;
    cudaGetSymbolAddress((void**)&ah,   g_ah);   cudaGetSymbolAddress((void**)&al,   g_al);
    cudaGetSymbolAddress((void**)&wth,  g_wth);  cudaGetSymbolAddress((void**)&wtl,  g_wtl);
    cudaGetSymbolAddress((void**)&qkvh, g_qkvh); cudaGetSymbolAddress((void**)&qkvl, g_qkvl);
    cudaGetSymbolAddress((void**)&vth,  g_vth);
    cudaGetSymbolAddress((void**)&ph,   g_ph);
    cudaGetSymbolAddress((void**)&s,    g_s);

    f16 *qh = qkvh,        *ql = qkvl;
    f16 *kh = qkvh + PSL,  *kl = qkvl + PSL;
    f16 *vh = qkvh + 2*PSL;

    cudaFuncSetAttribute(f16_gemm<OUT_SPLIT, true, true, true, 3>,
                         cudaFuncAttributeMaxDynamicSharedMemorySize, SMEM_FULL);
    cudaFuncSetAttribute(f16_gemm<OUT_F32, true, true, false, 3>,
                         cudaFuncAttributeMaxDynamicSharedMemorySize, SMEM_FULL);
    cudaFuncSetAttribute(f16_gemm<OUT_F32, false, false, false, 4>,
                         cudaFuncAttributeMaxDynamicSharedMemorySize, SMEM_PV);

    // 0) operand prep
    split_kernel<<<(long)M1 * DIM / 512, 256>>>(a, ah, al);
    {
        dim3 grid(DIM / 32, DIM / 32, 3);
        dim3 blk(32, 8, 1);
        wsplit_kernel<<<grid, blk>>>(w_q, w_k, w_v, wth, wtl);
    }

    // 1) ALL projections in ONE launch (z=0:Q, 1:K, 2:V)
    {
        dim3 grid(DIM / BN, M1 / BM, 3);
        f16_gemm<OUT_SPLIT, true, true, true, 3><<<grid, GTHREADS, SMEM_FULL>>>(
            ah, al, wth, wtl, b_q, b_k, b_v,
            nullptr, qkvh, qkvl, M1, DIM, DIM,
            0, (long)DIM * DIM, PSL);
    }

    // 2) vt = transpose(vh)
    {
        dim3 grid(DIM / 32, SEQ / 32, BATCH);
        dim3 blk(32, 8, 1);
        transpose_f16<<<grid, blk>>>((const uint16_t*)vh, (uint16_t*)vth,
                                     SEQ, DIM, (long)SEQ * DIM, (long)DIM * SEQ);
    }

    // 3) scores = q @ k^T (fp32 out, 3-term)
    {
        dim3 grid(SEQ / BN, SEQ / BM, BATCH);
        f16_gemm<OUT_F32, true, true, false, 3><<<grid, GTHREADS, SMEM_FULL>>>(
            qh, ql, kh, kl, nullptr, nullptr, nullptr,
            s, nullptr, nullptr,
            SEQ, SEQ, DIM, (long)SEQ * DIM, (long)SEQ * DIM, (long)SEQ * SEQ);
    }

    // 4) softmax -> single fp16 P
    softmax_f16<<<BATCH * SEQ, 256>>>(s, ph);

    // 5) out = P @ vt^T (fp32 out, 1-term, 4 CTAs/SM)
    {
        dim3 grid(DIM / BN, SEQ / BM, BATCH);
        f16_gemm<OUT_F32, false, false, false, 4><<<grid, GTHREADS, SMEM_PV>>>(
            ph, nullptr, vth, nullptr, nullptr, nullptr, nullptr,
            out, nullptr, nullptr,
            SEQ, DIM, SEQ, (long)SEQ * SEQ, (long)DIM * SEQ, (long)SEQ * DIM);
    }
}